// round 7
// baseline (speedup 1.0000x reference)
#include <cuda_runtime.h>
#include <cstdint>

// ---------------- problem constants ----------------
#define E_   16
#define B_   4096
#define DX_  128
#define DC_  64
#define DIN_ 192
#define DH_  1024
#define DO_  128

#define BM   128            // batch rows per CTA
#define CHN  32             // DH chunk
#define NCH  (DH_/CHN)      // 32 chunks
#define THREADS 128         // 4 warps, 32 rows each

// pair/row permutation within 8-groups: l -> ((l&3)<<1) | (l>>2)
#define PERM(l) ((((l)&3)<<1) | ((l)>>2))

// smem strides (floats), stride % 32 == 8 -> conflict-free LDS.64 fragment loads
#define SXC 200   // xc  [128][200]  pair-permuted tf32
#define SW1 200   // W1  [32][200]   prepacked tf32 (n sigma-permuted, k pair-permuted), x2 buf
#define SW2 40    // W2  [128][40]   prepacked tf32 (k pair-permuted), x2 buf

#define OFF_XC 0
#define N_XC   (BM*SXC)                  // 25600
#define OFF_W1 (OFF_XC + N_XC)           // 25600
#define N_W1B  (CHN*SW1)                 // 6400 per buf
#define OFF_W2 (OFF_W1 + 2*N_W1B)        // 38400
#define N_W2B  (DO_*SW2)                 // 5120 per buf
#define OFF_B1 (OFF_W2 + 2*N_W2B)        // 48640
#define OFF_B2 (OFF_B1 + DH_)            // 49664
#define SMEM_FLOATS (OFF_B2 + DO_)       // 49792
#define SMEM_BYTES  (SMEM_FLOATS*4)      // 199168

// ---------------- prepacked weight scratch (device globals: allowed) ----------------
__device__ float g_w1p[(size_t)E_ * DH_ * DIN_];   // 12.6 MB
__device__ float g_w2p[(size_t)E_ * DO_ * DH_];    //  8.4 MB
__device__ float g_b1p[E_ * DH_];

#define N1 (E_*DH_*DIN_)    // 3145728
#define N2 (E_*DO_*DH_)     // 2097152
#define N3 (E_*DH_)         // 16384
#define NPRE (N1 + N2 + N3) // 5259264 = 20544 * 256

// ---------------- helpers ----------------
__device__ __forceinline__ uint32_t s2u(const void* p){
    uint32_t a;
    asm("{ .reg .u64 t; cvta.to.shared.u64 t, %1; cvt.u32.u64 %0, t; }" : "=r"(a) : "l"(p));
    return a;
}
__device__ __forceinline__ uint32_t f2tf32(float f){
    uint32_t u; asm("cvt.rna.tf32.f32 %0, %1;" : "=r"(u) : "f"(f)); return u;
}
__device__ __forceinline__ float tf32f(float f){
    return __uint_as_float(f2tf32(f));
}
__device__ __forceinline__ uint32_t tf32relu_u(float v){
    return f2tf32(fmaxf(v, 0.0f));
}
// store one k-group of 8 (lo=k0..3, hi=k4..7) as pairs [0,4][1,5][2,6][3,7], tf32
__device__ __forceinline__ void put_group(float4 lo, float4 hi, float* dst){
    uint2 p;
    p.x = f2tf32(lo.x); p.y = f2tf32(hi.x); *(uint2*)(dst + 0) = p;
    p.x = f2tf32(lo.y); p.y = f2tf32(hi.y); *(uint2*)(dst + 2) = p;
    p.x = f2tf32(lo.z); p.y = f2tf32(hi.z); *(uint2*)(dst + 4) = p;
    p.x = f2tf32(lo.w); p.y = f2tf32(hi.w); *(uint2*)(dst + 6) = p;
}
__device__ __forceinline__ void cp16(uint32_t dst, const void* src){
    asm volatile("cp.async.cg.shared.global [%0], [%1], 16;" :: "r"(dst), "l"(src) : "memory");
}
#define CP_COMMIT() asm volatile("cp.async.commit_group;" ::: "memory")
#define CP_WAIT0()  asm volatile("cp.async.wait_group 0;" ::: "memory")
#define CP_WAIT1()  asm volatile("cp.async.wait_group 1;" ::: "memory")

__device__ __forceinline__ void mma_tf32(float c[4],
                                         uint32_t a0, uint32_t a1, uint32_t a2, uint32_t a3,
                                         uint32_t b0, uint32_t b1){
    asm volatile(
        "mma.sync.aligned.m16n8k8.row.col.f32.tf32.tf32.f32 "
        "{%0,%1,%2,%3}, {%4,%5,%6,%7}, {%8,%9}, {%0,%1,%2,%3};"
        : "+f"(c[0]), "+f"(c[1]), "+f"(c[2]), "+f"(c[3])
        : "r"(a0), "r"(a1), "r"(a2), "r"(a3), "r"(b0), "r"(b1));
}

// ---------------- prepack: W1/W2 -> tf32 + permutations, b1 -> permuted ----------------
__global__ __launch_bounds__(256)
void prepack_kernel(const float* __restrict__ W1, const float* __restrict__ b1,
                    const float* __restrict__ W2)
{
    const int i = blockIdx.x * 256 + threadIdx.x;
    if (i < N1) {
        const int k = i % DIN_;
        const int n = (i / DIN_) % DH_;
        const int e = i / (DIN_ * DH_);
        const int kp = (k & ~7) | PERM(k & 7);
        const int np = (n & ~7) | PERM(n & 7);   // sigma-permute rows: D cols land frag-ready
        g_w1p[((size_t)e * DH_ + np) * DIN_ + kp] = tf32f(W1[i]);
    } else if (i < N1 + N2) {
        const int j = i - N1;
        const int k = j % DH_;
        const int n = (j / DH_) % DO_;
        const int e = j / (DH_ * DO_);
        const int kp = (k & ~7) | PERM(k & 7);
        g_w2p[((size_t)e * DO_ + n) * DH_ + kp] = tf32f(W2[j]);
    } else if (i < NPRE) {
        const int j = i - N1 - N2;
        const int k = j % DH_;
        const int e = j / DH_;
        const int kp = (k & ~7) | PERM(k & 7);
        g_b1p[e * DH_ + kp] = b1[j];             // raw f32 value, permuted position
    }
}

// stage one DH chunk of prepacked W1 + W2 into smem buffer via cp.async
__device__ __forceinline__ void stage_w(uint32_t sb, const float* __restrict__ w1p,
                                        const float* __restrict__ w2p, int ch, int buf, int tid)
{
    const float* src1 = w1p + (size_t)ch * CHN * DIN_;
    const uint32_t d1 = sb + (OFF_W1 + buf * N_W1B) * 4;
    #pragma unroll
    for (int i = 0; i < 12; ++i) {                // 32 rows x 48 cp16 = 1536
        const int idx = tid + i * THREADS;
        const int r = idx / 48, j = idx % 48;
        cp16(d1 + r * (SW1*4) + j * 16, src1 + r * DIN_ + j * 4);
    }
    const float* src2 = w2p + (size_t)ch * CHN;   // k-window (8-group aligned)
    const uint32_t d2 = sb + (OFF_W2 + buf * N_W2B) * 4;
    #pragma unroll
    for (int i = 0; i < 8; ++i) {                 // 128 rows x 8 cp16 = 1024
        const int idx = tid + i * THREADS;
        const int r = idx / 8, j = idx % 8;
        cp16(d2 + r * (SW2*4) + j * 16, src2 + (size_t)r * DH_ + j * 4);
    }
}

// ---------------- main kernel ----------------
__global__ __launch_bounds__(THREADS, 1)
void expert_mlp_m32_kernel(const float* __restrict__ x, const float* __restrict__ cond,
                           const float* __restrict__ b2, float* __restrict__ out)
{
    extern __shared__ float sm[];
    float* s_xc = sm + OFF_XC;
    float* s_b1 = sm + OFF_B1;
    float* s_b2 = sm + OFF_B2;
    const uint32_t sb = s2u(sm);

    const int tid  = threadIdx.x;
    const int lane = tid & 31;
    const int wid  = tid >> 5;           // 0..3
    const int gr   = lane >> 2;
    const int ct   = lane & 3;

    const int e  = blockIdx.x >> 5;      // 32 CTAs per expert
    const int m0 = (blockIdx.x & 31) * BM;

    const float* xp  = x    + (size_t)e * B_ * DX_ + (size_t)m0 * DX_;
    const float* cp_ = cond + (size_t)e * B_ * DC_ + (size_t)m0 * DC_;
    const float* w1p = g_w1p + (size_t)e * DH_ * DIN_;
    const float* w2p = g_w2p + (size_t)e * DO_ * DH_;
    float*       op  = out  + (size_t)e * B_ * DO_ + (size_t)m0 * DO_;

    // stage chunk-0 weights first (overlaps with xc conversion below)
    stage_w(sb, w1p, w2p, 0, 0, tid);
    CP_COMMIT();

    // biases: full permuted b1 (f32), b2
    #pragma unroll
    for (int i = 0; i < 2; ++i) {
        const int t = tid + i * THREADS;
        const float4 v = *(const float4*)(g_b1p + e * DH_ + t * 4);
        *(float4*)(s_b1 + t * 4) = v;
    }
    if (tid < 32) {
        const float4 w = *(const float4*)(b2 + (size_t)e * DO_ + tid * 4);
        *(float4*)(s_b2 + tid * 4) = w;
    }

    // stage xc: pair-permuted tf32. 128 rows x 24 groups of 8
    #pragma unroll
    for (int i = 0; i < 24; ++i) {
        const int gi = tid + i * THREADS;
        const int r  = gi / 24, g = gi % 24;
        float4 lo, hi;
        if (g < 16) {
            lo = *(const float4*)(xp + (size_t)r * DX_ + g * 8);
            hi = *(const float4*)(xp + (size_t)r * DX_ + g * 8 + 4);
        } else {
            lo = *(const float4*)(cp_ + (size_t)r * DC_ + (g - 16) * 8);
            hi = *(const float4*)(cp_ + (size_t)r * DC_ + (g - 16) * 8 + 4);
        }
        put_group(lo, hi, s_xc + r * SXC + g * 8);
    }
    __syncthreads();

    // y accumulators: warp owns 32 rows x 128 cols -> 2 m-frags x 16 n-tiles x 4 regs
    float yacc[2][16][4];
    #pragma unroll
    for (int tm = 0; tm < 2; ++tm)
        #pragma unroll
        for (int t = 0; t < 16; ++t)
            #pragma unroll
            for (int c = 0; c < 4; ++c) yacc[tm][t][c] = 0.0f;

    const int arow = wid * 32 + gr;     // lower A row of m-frag 0 (m-frag 1 adds 16)
    const int kpo  = 2 * ct;            // pair offset within k-group

    for (int ch = 0; ch < NCH; ++ch) {
        const int buf = ch & 1;

        __syncthreads();                 // all warps done reading buf^1 (chunk ch-1)
        if (ch + 1 < NCH) {
            stage_w(sb, w1p, w2p, ch + 1, buf ^ 1, tid);
            CP_COMMIT();
            CP_WAIT1();                  // current buf's group complete
        } else {
            CP_WAIT0();
        }

        const float* w1s = sm + OFF_W1 + buf * N_W1B;
        const float* w2s = sm + OFF_W2 + buf * N_W2B;

        // ---- MMA1: h[32x32] = xc(warp rows) @ W1chunk^T ----
        float hacc[2][4][4];
        #pragma unroll
        for (int tm = 0; tm < 2; ++tm)
            #pragma unroll
            for (int t = 0; t < 4; ++t)
                #pragma unroll
                for (int c = 0; c < 4; ++c) hacc[tm][t][c] = 0.0f;

        #pragma unroll
        for (int kt = 0; kt < DIN_ / 8; ++kt) {
            const int kp = kt * 8 + kpo;
            uint32_t a[2][4];
            #pragma unroll
            for (int tm = 0; tm < 2; ++tm) {
                const float2 u = *(const float2*)(s_xc + (arow + tm * 16) * SXC + kp);
                const float2 v = *(const float2*)(s_xc + (arow + tm * 16 + 8) * SXC + kp);
                a[tm][0] = __float_as_uint(u.x);
                a[tm][1] = __float_as_uint(v.x);
                a[tm][2] = __float_as_uint(u.y);
                a[tm][3] = __float_as_uint(v.y);
            }
            #pragma unroll
            for (int tn = 0; tn < 4; ++tn) {
                const float2 b = *(const float2*)(w1s + (tn * 8 + gr) * SW1 + kp);
                const uint32_t b0 = __float_as_uint(b.x);
                const uint32_t b1v = __float_as_uint(b.y);
                mma_tf32(hacc[0][tn], a[0][0], a[0][1], a[0][2], a[0][3], b0, b1v);
                mma_tf32(hacc[1][tn], a[1][0], a[1][1], a[1][2], a[1][3], b0, b1v);
            }
        }

        // ---- register epilogue: relu(h + b1) -> tf32, reorder D->A (free) ----
        uint32_t ah[2][4][4];
        const float* b1s = s_b1 + ch * CHN;
        #pragma unroll
        for (int t = 0; t < 4; ++t) {
            const float2 bb = *(const float2*)(b1s + t * 8 + kpo);  // (b[ct], b[ct+4])
            #pragma unroll
            for (int tm = 0; tm < 2; ++tm) {
                ah[tm][t][0] = tf32relu_u(hacc[tm][t][0] + bb.x);   // a0 = d0
                ah[tm][t][2] = tf32relu_u(hacc[tm][t][1] + bb.y);   // a2 = d1
                ah[tm][t][1] = tf32relu_u(hacc[tm][t][2] + bb.x);   // a1 = d2
                ah[tm][t][3] = tf32relu_u(hacc[tm][t][3] + bb.y);   // a3 = d3
            }
        }

        // ---- MMA2: y[32x128] += h(frags in regs) @ W2chunk^T ----
        #pragma unroll
        for (int t = 0; t < 4; ++t) {
            const int kb = t * 8 + kpo;
            #pragma unroll
            for (int tn = 0; tn < 16; ++tn) {
                const float2 b = *(const float2*)(w2s + (tn * 8 + gr) * SW2 + kb);
                const uint32_t b0 = __float_as_uint(b.x);
                const uint32_t b1v = __float_as_uint(b.y);
                mma_tf32(yacc[0][tn], ah[0][t][0], ah[0][t][1], ah[0][t][2], ah[0][t][3], b0, b1v);
                mma_tf32(yacc[1][tn], ah[1][t][0], ah[1][t][1], ah[1][t][2], ah[1][t][3], b0, b1v);
            }
        }
    }

    // ---- final epilogue: y + b2 -> gmem ----
    #pragma unroll
    for (int tn = 0; tn < 16; ++tn) {
        const int col = tn * 8 + 2 * ct;
        const float2 bb = *(const float2*)(s_b2 + col);
        #pragma unroll
        for (int tm = 0; tm < 2; ++tm) {
            const int row = arow + tm * 16;
            float2 lo, hi;
            lo.x = yacc[tm][tn][0] + bb.x;
            lo.y = yacc[tm][tn][1] + bb.y;
            hi.x = yacc[tm][tn][2] + bb.x;
            hi.y = yacc[tm][tn][3] + bb.y;
            *(float2*)(op + (size_t)row * DO_ + col)       = lo;
            *(float2*)(op + (size_t)(row + 8) * DO_ + col) = hi;
        }
    }
}

extern "C" void kernel_launch(void* const* d_in, const int* in_sizes, int n_in,
                              void* d_out, int out_size)
{
    const float* x    = (const float*)d_in[0];
    const float* cond = (const float*)d_in[1];
    const float* W1   = (const float*)d_in[2];
    const float* b1   = (const float*)d_in[3];
    const float* W2   = (const float*)d_in[4];
    const float* b2   = (const float*)d_in[5];
    float* out = (float*)d_out;

    prepack_kernel<<<NPRE / 256, 256>>>(W1, b1, W2);

    cudaFuncSetAttribute(expert_mlp_m32_kernel,
                         cudaFuncAttributeMaxDynamicSharedMemorySize, SMEM_BYTES);
    const int grid = E_ * (B_ / BM);   // 512 CTAs
    expert_mlp_m32_kernel<<<grid, THREADS, SMEM_BYTES>>>(x, cond, b2, out);
}

// round 8
// speedup vs baseline: 1.0191x; 1.0191x over previous
#include <cuda_runtime.h>
#include <cstdint>

// ---------------- problem constants ----------------
#define E_   16
#define B_   4096
#define DX_  128
#define DC_  64
#define DIN_ 192
#define DH_  1024
#define DO_  128

#define BM   128            // batch rows per CTA
#define CHN  32             // DH chunk
#define NCH  (DH_/CHN)      // 32 chunks
#define THREADS 256         // 8 warps x 16 rows

// row permutation within 8-groups (sigma): l -> ((l&3)<<1) | (l>>2)
#define PERM(l) ((((l)&3)<<1) | ((l)>>2))

// kt-pair interleaved k position: k -> (ktpair)*16 + ct*4 + (kt&1)*2 + h
// where kt=k>>3, ct=k&3, h=(k>>2)&1. One LDS.128 at ktpair*16+4*ct yields
// fragments for BOTH k-groups 2p and 2p+1: [even_k0, even_k4, odd_k0, odd_k4].
__host__ __device__ __forceinline__ int kpos(int k){
    const int kt = k >> 3, ct = k & 3, h = (k >> 2) & 1;
    return (kt >> 1) * 16 + ct * 4 + ((kt & 1) << 1) + h;
}

// smem row strides (floats) == 16 mod 32 -> conflict-free LDS.128 fragment loads
#define SXC 208   // xc  [128][208]  interleaved tf32
#define SW1 208   // W1  [32][208]   prepacked tf32, x2 buf
#define SW2 48    // W2  [128][48]   prepacked tf32, x2 buf

#define OFF_XC 0
#define N_XC   (BM*SXC)                  // 26624
#define OFF_W1 (OFF_XC + N_XC)           // 26624
#define N_W1B  (CHN*SW1)                 // 6656 per buf
#define OFF_W2 (OFF_W1 + 2*N_W1B)        // 39936
#define N_W2B  (DO_*SW2)                 // 6144 per buf
#define OFF_B1 (OFF_W2 + 2*N_W2B)        // 52224
#define OFF_B2 (OFF_B1 + DH_)            // 53248
#define SMEM_FLOATS (OFF_B2 + DO_)       // 53376
#define SMEM_BYTES  (SMEM_FLOATS*4)      // 213504

// ---------------- prepacked weight scratch (device globals: allowed) ----------------
__device__ float g_w1p[(size_t)E_ * DH_ * DIN_];   // 12.6 MB
__device__ float g_w2p[(size_t)E_ * DO_ * DH_];    //  8.4 MB
__device__ float g_b1p[E_ * DH_];

#define N1 (E_*DH_*DIN_)    // 3145728
#define N2 (E_*DO_*DH_)     // 2097152
#define N3 (E_*DH_)         // 16384
#define NPRE (N1 + N2 + N3) // 5259264 = 20544 * 256

// ---------------- helpers ----------------
__device__ __forceinline__ uint32_t s2u(const void* p){
    uint32_t a;
    asm("{ .reg .u64 t; cvta.to.shared.u64 t, %1; cvt.u32.u64 %0, t; }" : "=r"(a) : "l"(p));
    return a;
}
__device__ __forceinline__ uint32_t f2tf32(float f){
    uint32_t u; asm("cvt.rna.tf32.f32 %0, %1;" : "=r"(u) : "f"(f)); return u;
}
__device__ __forceinline__ float tf32f(float f){
    return __uint_as_float(f2tf32(f));
}
__device__ __forceinline__ uint32_t tf32relu_u(float v){
    return f2tf32(fmaxf(v, 0.0f));
}
__device__ __forceinline__ void cp16(uint32_t dst, const void* src){
    asm volatile("cp.async.cg.shared.global [%0], [%1], 16;" :: "r"(dst), "l"(src) : "memory");
}
#define CP_COMMIT() asm volatile("cp.async.commit_group;" ::: "memory")
#define CP_WAIT0()  asm volatile("cp.async.wait_group 0;" ::: "memory")
#define CP_WAIT1()  asm volatile("cp.async.wait_group 1;" ::: "memory")

__device__ __forceinline__ void mma_tf32(float c[4],
                                         uint32_t a0, uint32_t a1, uint32_t a2, uint32_t a3,
                                         uint32_t b0, uint32_t b1){
    asm volatile(
        "mma.sync.aligned.m16n8k8.row.col.f32.tf32.tf32.f32 "
        "{%0,%1,%2,%3}, {%4,%5,%6,%7}, {%8,%9}, {%0,%1,%2,%3};"
        : "+f"(c[0]), "+f"(c[1]), "+f"(c[2]), "+f"(c[3])
        : "r"(a0), "r"(a1), "r"(a2), "r"(a3), "r"(b0), "r"(b1));
}

// ---------------- prepack: W1/W2 -> tf32 + interleave, b1 -> sigma ----------------
__global__ __launch_bounds__(256)
void prepack_kernel(const float* __restrict__ W1, const float* __restrict__ b1,
                    const float* __restrict__ W2)
{
    const int i = blockIdx.x * 256 + threadIdx.x;
    if (i < N1) {
        const int k = i % DIN_;
        const int n = (i / DIN_) % DH_;
        const int e = i / (DIN_ * DH_);
        const int np = (n & ~7) | PERM(n & 7);   // sigma-permute rows: D cols frag-ready
        g_w1p[((size_t)e * DH_ + np) * DIN_ + kpos(k)] = tf32f(W1[i]);
    } else if (i < N1 + N2) {
        const int j = i - N1;
        const int k = j % DH_;
        const int n = (j / DH_) % DO_;
        const int e = j / (DH_ * DO_);
        const int ch = k >> 5;                    // chunk, 32-wide window
        const int kpl = kpos(k & 31);             // interleave within window
        g_w2p[((size_t)e * DO_ + n) * DH_ + ch * 32 + kpl] = tf32f(W2[j]);
    } else if (i < NPRE) {
        const int j = i - N1 - N2;
        const int k = j % DH_;
        const int e = j / DH_;
        const int kp = (k & ~7) | PERM(k & 7);   // bias stays in sigma'd col space
        g_b1p[e * DH_ + kp] = b1[j];
    }
}

// stage one DH chunk of prepacked W1 + W2 into smem buffer via cp.async
__device__ __forceinline__ void stage_w(uint32_t sb, const float* __restrict__ w1p,
                                        const float* __restrict__ w2p, int ch, int buf, int tid)
{
    const float* src1 = w1p + (size_t)ch * CHN * DIN_;
    const uint32_t d1 = sb + (OFF_W1 + buf * N_W1B) * 4;
    #pragma unroll
    for (int i = 0; i < 6; ++i) {                 // 32 rows x 48 cp16 = 1536
        const int idx = tid + i * THREADS;
        const int r = idx / 48, j = idx % 48;
        cp16(d1 + r * (SW1*4) + j * 16, src1 + r * DIN_ + j * 4);
    }
    const float* src2 = w2p + (size_t)ch * 32;    // contiguous 32-float window per row
    const uint32_t d2 = sb + (OFF_W2 + buf * N_W2B) * 4;
    #pragma unroll
    for (int i = 0; i < 4; ++i) {                 // 128 rows x 8 cp16 = 1024
        const int idx = tid + i * THREADS;
        const int r = idx / 8, j = idx % 8;
        cp16(d2 + r * (SW2*4) + j * 16, src2 + (size_t)r * DH_ + j * 4);
    }
}

// ---------------- main kernel ----------------
__global__ __launch_bounds__(THREADS, 1)
void expert_mlp_ilv_kernel(const float* __restrict__ x, const float* __restrict__ cond,
                           const float* __restrict__ b2, float* __restrict__ out)
{
    extern __shared__ float sm[];
    float* s_xc = sm + OFF_XC;
    float* s_b1 = sm + OFF_B1;
    float* s_b2 = sm + OFF_B2;
    const uint32_t sb = s2u(sm);

    const int tid  = threadIdx.x;
    const int lane = tid & 31;
    const int wid  = tid >> 5;           // 0..7, 16 rows each
    const int gr   = lane >> 2;
    const int ct   = lane & 3;

    const int e  = blockIdx.x >> 5;      // 32 CTAs per expert
    const int m0 = (blockIdx.x & 31) * BM;

    const float* xp  = x    + (size_t)e * B_ * DX_ + (size_t)m0 * DX_;
    const float* cp_ = cond + (size_t)e * B_ * DC_ + (size_t)m0 * DC_;
    const float* w1p = g_w1p + (size_t)e * DH_ * DIN_;
    const float* w2p = g_w2p + (size_t)e * DO_ * DH_;
    float*       op  = out  + (size_t)e * B_ * DO_ + (size_t)m0 * DO_;

    // stage chunk-0 weights first (overlaps with xc conversion below)
    stage_w(sb, w1p, w2p, 0, 0, tid);
    CP_COMMIT();

    // biases: full sigma'd b1 (f32), b2
    {
        const float4 v = *(const float4*)(g_b1p + e * DH_ + tid * 4);
        *(float4*)(s_b1 + tid * 4) = v;
        if (tid < 32) {
            const float4 w = *(const float4*)(b2 + (size_t)e * DO_ + tid * 4);
            *(float4*)(s_b2 + tid * 4) = w;
        }
    }

    // stage xc: kt-pair interleaved tf32. 128 rows x 12 blocks of 16 k
    #pragma unroll
    for (int i = 0; i < 6; ++i) {
        const int gi = tid + i * THREADS;          // 1536 blocks
        const int r  = gi / 12, p = gi % 12;
        float4 f0, f1, f2, f3;                      // k = 16p .. 16p+15
        if (p < 8) {
            const float* s = xp + (size_t)r * DX_ + p * 16;
            f0 = *(const float4*)(s);      f1 = *(const float4*)(s + 4);
            f2 = *(const float4*)(s + 8);  f3 = *(const float4*)(s + 12);
        } else {
            const float* s = cp_ + (size_t)r * DC_ + (p - 8) * 16;
            f0 = *(const float4*)(s);      f1 = *(const float4*)(s + 4);
            f2 = *(const float4*)(s + 8);  f3 = *(const float4*)(s + 12);
        }
        // even group (kt=2p): k0..3 = f0, k4..7 = f1; odd group: f2, f3
        float* d = s_xc + r * SXC + p * 16;
        const float ev0[4] = {f0.x, f0.y, f0.z, f0.w};
        const float ev4[4] = {f1.x, f1.y, f1.z, f1.w};
        const float od0[4] = {f2.x, f2.y, f2.z, f2.w};
        const float od4[4] = {f3.x, f3.y, f3.z, f3.w};
        #pragma unroll
        for (int c = 0; c < 4; ++c) {
            uint4 q;
            q.x = f2tf32(ev0[c]); q.y = f2tf32(ev4[c]);
            q.z = f2tf32(od0[c]); q.w = f2tf32(od4[c]);
            *(uint4*)(d + c * 4) = q;
        }
    }
    __syncthreads();

    // y accumulators: warp owns 16 rows x 128 cols -> 16 n-tiles x 4 regs
    float yacc[16][4];
    #pragma unroll
    for (int t = 0; t < 16; ++t)
        #pragma unroll
        for (int c = 0; c < 4; ++c) yacc[t][c] = 0.0f;

    const int arow = wid * 16 + gr;     // this thread's lower A row
    const int fq   = 4 * ct;            // float4 offset within 16-float ktpair block

    for (int ch = 0; ch < NCH; ++ch) {
        const int buf = ch & 1;

        __syncthreads();                 // all warps done reading buf^1 (chunk ch-1)
        if (ch + 1 < NCH) {
            stage_w(sb, w1p, w2p, ch + 1, buf ^ 1, tid);
            CP_COMMIT();
            CP_WAIT1();                  // current buf's group complete
        } else {
            CP_WAIT0();
        }

        const float* w1s = sm + OFF_W1 + buf * N_W1B;
        const float* w2s = sm + OFF_W2 + buf * N_W2B;

        // ---- MMA1: h[16x32] = xc(warp rows) @ W1chunk^T, split even/odd chains ----
        float haccE[4][4], haccO[4][4];
        #pragma unroll
        for (int t = 0; t < 4; ++t)
            #pragma unroll
            for (int c = 0; c < 4; ++c) { haccE[t][c] = 0.0f; haccO[t][c] = 0.0f; }

        #pragma unroll
        for (int p = 0; p < 12; ++p) {           // 12 ktpairs = K 192
            const int kb = p * 16 + fq;
            const float4 u = *(const float4*)(s_xc + arow * SXC + kb);
            const float4 v = *(const float4*)(s_xc + (arow + 8) * SXC + kb);
            const uint32_t ae0 = __float_as_uint(u.x), ae1 = __float_as_uint(v.x);
            const uint32_t ae2 = __float_as_uint(u.y), ae3 = __float_as_uint(v.y);
            const uint32_t ao0 = __float_as_uint(u.z), ao1 = __float_as_uint(v.z);
            const uint32_t ao2 = __float_as_uint(u.w), ao3 = __float_as_uint(v.w);
            #pragma unroll
            for (int tn = 0; tn < 4; ++tn) {
                const float4 b = *(const float4*)(w1s + (tn * 8 + gr) * SW1 + kb);
                mma_tf32(haccE[tn], ae0, ae1, ae2, ae3,
                         __float_as_uint(b.x), __float_as_uint(b.y));
                mma_tf32(haccO[tn], ao0, ao1, ao2, ao3,
                         __float_as_uint(b.z), __float_as_uint(b.w));
            }
        }

        // ---- register epilogue: relu(hE+hO + b1) -> tf32, reorder D->A (free) ----
        uint32_t ah[4][4];
        const float* b1s = s_b1 + ch * CHN;
        #pragma unroll
        for (int t = 0; t < 4; ++t) {
            const float2 bb = *(const float2*)(b1s + t * 8 + 2 * ct);
            ah[t][0] = tf32relu_u(haccE[t][0] + haccO[t][0] + bb.x);  // a0 = d0
            ah[t][2] = tf32relu_u(haccE[t][1] + haccO[t][1] + bb.y);  // a2 = d1
            ah[t][1] = tf32relu_u(haccE[t][2] + haccO[t][2] + bb.x);  // a1 = d2
            ah[t][3] = tf32relu_u(haccE[t][3] + haccO[t][3] + bb.y);  // a3 = d3
        }

        // ---- MMA2: y[16x128] += h(frags in regs) @ W2chunk^T ----
        #pragma unroll
        for (int p = 0; p < 2; ++p) {            // 2 ktpairs = K 32
            const int kb = p * 16 + fq;
            const uint32_t* aE = ah[2 * p];
            const uint32_t* aO = ah[2 * p + 1];
            #pragma unroll
            for (int tn = 0; tn < 16; ++tn) {
                const float4 b = *(const float4*)(w2s + (tn * 8 + gr) * SW2 + kb);
                mma_tf32(yacc[tn], aE[0], aE[1], aE[2], aE[3],
                         __float_as_uint(b.x), __float_as_uint(b.y));
                mma_tf32(yacc[tn], aO[0], aO[1], aO[2], aO[3],
                         __float_as_uint(b.z), __float_as_uint(b.w));
            }
        }
    }

    // ---- final epilogue: y + b2 -> gmem ----
    #pragma unroll
    for (int tn = 0; tn < 16; ++tn) {
        const int col = tn * 8 + 2 * ct;
        const float2 bb = *(const float2*)(s_b2 + col);
        float2 lo, hi;
        lo.x = yacc[tn][0] + bb.x;
        lo.y = yacc[tn][1] + bb.y;
        hi.x = yacc[tn][2] + bb.x;
        hi.y = yacc[tn][3] + bb.y;
        *(float2*)(op + (size_t)arow * DO_ + col)       = lo;
        *(float2*)(op + (size_t)(arow + 8) * DO_ + col) = hi;
    }
}

extern "C" void kernel_launch(void* const* d_in, const int* in_sizes, int n_in,
                              void* d_out, int out_size)
{
    const float* x    = (const float*)d_in[0];
    const float* cond = (const float*)d_in[1];
    const float* W1   = (const float*)d_in[2];
    const float* b1   = (const float*)d_in[3];
    const float* W2   = (const float*)d_in[4];
    const float* b2   = (const float*)d_in[5];
    float* out = (float*)d_out;

    prepack_kernel<<<NPRE / 256, 256>>>(W1, b1, W2);

    cudaFuncSetAttribute(expert_mlp_ilv_kernel,
                         cudaFuncAttributeMaxDynamicSharedMemorySize, SMEM_BYTES);
    const int grid = E_ * (B_ / BM);   // 512 CTAs
    expert_mlp_ilv_kernel<<<grid, THREADS, SMEM_BYTES>>>(x, cond, b2, out);
}

// round 9
// speedup vs baseline: 2.0135x; 1.9757x over previous
#include <cuda_runtime.h>
#include <cuda_fp16.h>
#include <cstdint>

// ---------------- problem constants ----------------
#define E_   16
#define B_   4096
#define DX_  128
#define DC_  64
#define DIN_ 192
#define DH_  1024
#define DO_  128

#define BM   128            // batch rows per CTA
#define CHN  32             // DH chunk
#define NCH  (DH_/CHN)      // 32 chunks
#define THREADS 256         // 8 warps x 16 rows

// ---------------- smem layout (bytes) ----------------
// fragment-load strides: bytes ≡ 32 or 96 (mod 128) -> conflict-free LDS.64
#define SXC_B 416   // xc row: 192 halves + pad (208 halves)
#define SW1_B 416   // W1 row: 192 halves + pad
#define SW2_B 96    // W2 row: 32 halves + pad (48 halves)

#define OFF_XC 0
#define XC_BYTES (BM*SXC_B)            // 53248
#define OFF_W1 (OFF_XC + XC_BYTES)     // 53248
#define W1_BYTES (CHN*SW1_B)           // 13312 per buf
#define OFF_W2 (OFF_W1 + 2*W1_BYTES)   // 79872
#define W2_BYTES (DO_*SW2_B)           // 12288 per buf
#define OFF_B1 (OFF_W2 + 2*W2_BYTES)   // 104448 (fp32 b1)
#define OFF_B2 (OFF_B1 + DH_*4)        // 108544 (fp32 b2)
#define SMEM_BYTES (OFF_B2 + DO_*4)    // 109056

// ---------------- prepacked fp16 scratch (device globals: allowed) ----------------
__device__ __half g_xch[(size_t)E_ * B_ * DIN_];   // 25.2 MB (per-call)
__device__ __half g_w1h[(size_t)E_ * DH_ * DIN_];  //  6.3 MB
__device__ __half g_w2h[(size_t)E_ * DO_ * DH_];   //  4.2 MB

// prepack blocks of 16 k-values
#define NB1 (E_*DH_*(DIN_/16))     // 196608
#define NB2 (E_*DO_*(DH_/16))      // 131072
#define NBX (E_*B_*(DIN_/16))      // 786432
#define NBTOT (NB1+NB2+NBX)        // 1114112 = 4352*256

// ---------------- helpers ----------------
__device__ __forceinline__ uint32_t s2u(const void* p){
    uint32_t a;
    asm("{ .reg .u64 t; cvta.to.shared.u64 t, %1; cvt.u32.u64 %0, t; }" : "=r"(a) : "l"(p));
    return a;
}
__device__ __forceinline__ uint32_t pkh2(float lo, float hi){
    __half2 h = __floats2half2_rn(lo, hi);       // lo -> lower 16 bits
    return *reinterpret_cast<uint32_t*>(&h);
}
__device__ __forceinline__ void cp16(uint32_t dst, const void* src){
    asm volatile("cp.async.cg.shared.global [%0], [%1], 16;" :: "r"(dst), "l"(src) : "memory");
}
#define CP_COMMIT() asm volatile("cp.async.commit_group;" ::: "memory")
#define CP_WAIT0()  asm volatile("cp.async.wait_group 0;" ::: "memory")
#define CP_WAIT1()  asm volatile("cp.async.wait_group 1;" ::: "memory")

__device__ __forceinline__ void mma_fp16(float c[4],
                                         uint32_t a0, uint32_t a1, uint32_t a2, uint32_t a3,
                                         uint32_t b0, uint32_t b1){
    asm volatile(
        "mma.sync.aligned.m16n8k16.row.col.f32.f16.f16.f32 "
        "{%0,%1,%2,%3}, {%4,%5,%6,%7}, {%8,%9}, {%0,%1,%2,%3};"
        : "+f"(c[0]), "+f"(c[1]), "+f"(c[2]), "+f"(c[3])
        : "r"(a0), "r"(a1), "r"(a2), "r"(a3), "r"(b0), "r"(b1));
}

// ---------------- prepack: fp32 -> fp16, k-interleaved in 16-blocks ----------------
// block layout (halves): [k0,k1, k8,k9, k2,k3, k10,k11, k4,k5, k12,k13, k6,k7, k14,k15]
// => thread ct's LDS.64 at byte 8*ct yields (pair k=2ct,2ct+1 ; pair k=2ct+8,2ct+9)
__global__ __launch_bounds__(256)
void prepack_kernel(const float* __restrict__ x, const float* __restrict__ cond,
                    const float* __restrict__ W1, const float* __restrict__ W2)
{
    const int i = blockIdx.x * 256 + threadIdx.x;
    if (i >= NBTOT) return;

    const float* s;
    __half* dst;
    if (i < NB1) {
        const int p = i % (DIN_/16);
        const int n = (i / (DIN_/16)) % DH_;
        const int e = i / ((DIN_/16) * DH_);
        s   = W1 + ((size_t)e * DH_ + n) * DIN_ + p * 16;
        dst = g_w1h + ((size_t)e * DH_ + n) * DIN_ + p * 16;
    } else if (i < NB1 + NB2) {
        const int j = i - NB1;
        const int p = j % (DH_/16);
        const int n = (j / (DH_/16)) % DO_;
        const int e = j / ((DH_/16) * DO_);
        s   = W2 + ((size_t)e * DO_ + n) * DH_ + p * 16;
        dst = g_w2h + ((size_t)e * DO_ + n) * DH_ + p * 16;
    } else {
        const int j = i - NB1 - NB2;
        const int p = j % (DIN_/16);
        const int r = (j / (DIN_/16)) % B_;
        const int e = j / ((DIN_/16) * B_);
        s = (p < 8) ? (x    + ((size_t)e * B_ + r) * DX_ + p * 16)
                    : (cond + ((size_t)e * B_ + r) * DC_ + (p - 8) * 16);
        dst = g_xch + ((size_t)e * B_ + r) * DIN_ + p * 16;
    }

    const float4 f0 = *(const float4*)(s);
    const float4 f1 = *(const float4*)(s + 4);
    const float4 f2 = *(const float4*)(s + 8);
    const float4 f3 = *(const float4*)(s + 12);
    uint4 o0, o1;
    o0.x = pkh2(f0.x, f0.y);   // k0,k1
    o0.y = pkh2(f2.x, f2.y);   // k8,k9
    o0.z = pkh2(f0.z, f0.w);   // k2,k3
    o0.w = pkh2(f2.z, f2.w);   // k10,k11
    o1.x = pkh2(f1.x, f1.y);   // k4,k5
    o1.y = pkh2(f3.x, f3.y);   // k12,k13
    o1.z = pkh2(f1.z, f1.w);   // k6,k7
    o1.w = pkh2(f3.z, f3.w);   // k14,k15
    ((uint4*)dst)[0] = o0;
    ((uint4*)dst)[1] = o1;
}

// stage one DH chunk of prepacked W1 + W2 into smem buffer via cp.async
__device__ __forceinline__ void stage_w(uint32_t sb, const __half* __restrict__ w1h,
                                        const __half* __restrict__ w2h, int ch, int buf, int tid)
{
    const __half* src1 = w1h + (size_t)ch * CHN * DIN_;
    const uint32_t d1 = sb + OFF_W1 + buf * W1_BYTES;
    #pragma unroll
    for (int i = 0; i < 3; ++i) {                 // 32 rows x 24 cp16 = 768
        const int idx = tid + i * THREADS;
        const int r = idx / 24, j = idx % 24;
        cp16(d1 + r * SW1_B + j * 16, src1 + (size_t)r * DIN_ + j * 8);
    }
    const __half* src2 = w2h + (size_t)ch * CHN;  // 32-half window per row
    const uint32_t d2 = sb + OFF_W2 + buf * W2_BYTES;
    #pragma unroll
    for (int i = 0; i < 2; ++i) {                 // 128 rows x 4 cp16 = 512
        const int idx = tid + i * THREADS;
        const int r = idx / 4, j = idx % 4;
        cp16(d2 + r * SW2_B + j * 16, src2 + (size_t)r * DH_ + j * 8);
    }
}

// ---------------- main kernel ----------------
__global__ __launch_bounds__(THREADS)
void expert_mlp_fp16_kernel(const float* __restrict__ b1, const float* __restrict__ b2,
                            float* __restrict__ out)
{
    extern __shared__ char smem[];
    float* s_b1 = (float*)(smem + OFF_B1);
    float* s_b2 = (float*)(smem + OFF_B2);
    const uint32_t sb = s2u(smem);

    const int tid  = threadIdx.x;
    const int lane = tid & 31;
    const int wid  = tid >> 5;           // 0..7, 16 rows each
    const int gr   = lane >> 2;
    const int ct   = lane & 3;

    const int e  = blockIdx.x >> 5;      // 32 CTAs per expert
    const int m0 = (blockIdx.x & 31) * BM;

    const __half* xch = g_xch + ((size_t)e * B_ + m0) * DIN_;
    const __half* w1h = g_w1h + (size_t)e * DH_ * DIN_;
    const __half* w2h = g_w2h + (size_t)e * DO_ * DH_;
    float*        op  = out  + (size_t)e * B_ * DO_ + (size_t)m0 * DO_;

    // stage chunk-0 weights + xc tile (all prepacked fp16) via cp.async
    stage_w(sb, w1h, w2h, 0, 0, tid);
    #pragma unroll
    for (int i = 0; i < 12; ++i) {                 // 128 rows x 24 cp16 = 3072
        const int idx = tid + i * THREADS;
        const int r = idx / 24, j = idx % 24;
        cp16(sb + OFF_XC + r * SXC_B + j * 16, xch + (size_t)r * DIN_ + j * 8);
    }
    CP_COMMIT();

    // biases (fp32, natural order)
    {
        const float4 v = *(const float4*)(b1 + (size_t)e * DH_ + tid * 4);
        *(float4*)(s_b1 + tid * 4) = v;
        if (tid < 32) {
            const float4 w = *(const float4*)(b2 + (size_t)e * DO_ + tid * 4);
            *(float4*)(s_b2 + tid * 4) = w;
        }
    }
    CP_WAIT0();
    __syncthreads();

    // y accumulators: warp owns 16 rows x 128 cols -> 16 n-tiles x 4 regs
    float yacc[16][4];
    #pragma unroll
    for (int t = 0; t < 16; ++t)
        #pragma unroll
        for (int c = 0; c < 4; ++c) yacc[t][c] = 0.0f;

    const int arow = wid * 16 + gr;      // this thread's lower A row
    const char* sxc = smem + OFF_XC;

    for (int ch = 0; ch < NCH; ++ch) {
        const int buf = ch & 1;

        __syncthreads();                 // all warps done reading buf^1 (chunk ch-1)
        if (ch + 1 < NCH) {
            stage_w(sb, w1h, w2h, ch + 1, buf ^ 1, tid);
            CP_COMMIT();
            CP_WAIT1();                  // current buf's group complete
        } else {
            CP_WAIT0();
        }

        const char* w1s = smem + OFF_W1 + buf * W1_BYTES;
        const char* w2s = smem + OFF_W2 + buf * W2_BYTES;

        // ---- MMA1: h[16x32] = xc(warp rows) @ W1chunk^T  (K=192 = 12 k16-steps) ----
        float hacc[4][4];
        #pragma unroll
        for (int t = 0; t < 4; ++t)
            #pragma unroll
            for (int c = 0; c < 4; ++c) hacc[t][c] = 0.0f;

        #pragma unroll
        for (int kt = 0; kt < 12; ++kt) {
            const int off = kt * 32 + ct * 8;
            const uint2 ua = *(const uint2*)(sxc + arow * SXC_B + off);       // a0|a2
            const uint2 ub = *(const uint2*)(sxc + (arow + 8) * SXC_B + off); // a1|a3
            #pragma unroll
            for (int tn = 0; tn < 4; ++tn) {
                const uint2 bw = *(const uint2*)(w1s + (tn * 8 + gr) * SW1_B + off);
                mma_fp16(hacc[tn], ua.x, ub.x, ua.y, ub.y, bw.x, bw.y);
            }
        }

        // ---- register epilogue: relu(h + b1) -> fp16 pairs (frag-ready, no permute) ----
        uint32_t pk[4][2];
        const float* b1s = s_b1 + ch * CHN;
        #pragma unroll
        for (int t = 0; t < 4; ++t) {
            const float2 bb = *(const float2*)(b1s + t * 8 + 2 * ct);
            pk[t][0] = pkh2(fmaxf(hacc[t][0] + bb.x, 0.0f),
                            fmaxf(hacc[t][1] + bb.y, 0.0f));   // row gr,   cols 2ct,2ct+1
            pk[t][1] = pkh2(fmaxf(hacc[t][2] + bb.x, 0.0f),
                            fmaxf(hacc[t][3] + bb.y, 0.0f));   // row gr+8
        }

        // ---- MMA2: y[16x128] += h(frags in regs) @ W2chunk^T (K=32 = 2 k16-steps) ----
        #pragma unroll
        for (int ks = 0; ks < 2; ++ks) {
            const uint32_t a0 = pk[2 * ks][0];     // row gr,   k 2ct..+1
            const uint32_t a1 = pk[2 * ks][1];     // row gr+8
            const uint32_t a2 = pk[2 * ks + 1][0]; // row gr,   k 2ct+8..+9
            const uint32_t a3 = pk[2 * ks + 1][1]; // row gr+8
            const int off = ks * 32 + ct * 8;
            #pragma unroll
            for (int tn = 0; tn < 16; ++tn) {
                const uint2 bw = *(const uint2*)(w2s + (tn * 8 + gr) * SW2_B + off);
                mma_fp16(yacc[tn], a0, a1, a2, a3, bw.x, bw.y);
            }
        }
    }

    // ---- final epilogue: y + b2 -> gmem ----
    #pragma unroll
    for (int tn = 0; tn < 16; ++tn) {
        const int col = tn * 8 + 2 * ct;
        const float2 bb = *(const float2*)(s_b2 + col);
        float2 lo, hi;
        lo.x = yacc[tn][0] + bb.x;
        lo.y = yacc[tn][1] + bb.y;
        hi.x = yacc[tn][2] + bb.x;
        hi.y = yacc[tn][3] + bb.y;
        *(float2*)(op + (size_t)arow * DO_ + col)       = lo;
        *(float2*)(op + (size_t)(arow + 8) * DO_ + col) = hi;
    }
}

extern "C" void kernel_launch(void* const* d_in, const int* in_sizes, int n_in,
                              void* d_out, int out_size)
{
    const float* x    = (const float*)d_in[0];
    const float* cond = (const float*)d_in[1];
    const float* W1   = (const float*)d_in[2];
    const float* b1   = (const float*)d_in[3];
    const float* W2   = (const float*)d_in[4];
    const float* b2   = (const float*)d_in[5];
    float* out = (float*)d_out;

    prepack_kernel<<<(NBTOT + 255) / 256, 256>>>(x, cond, W1, W2);

    cudaFuncSetAttribute(expert_mlp_fp16_kernel,
                         cudaFuncAttributeMaxDynamicSharedMemorySize, SMEM_BYTES);
    const int grid = E_ * (B_ / BM);   // 512 CTAs
    expert_mlp_fp16_kernel<<<grid, THREADS, SMEM_BYTES>>>(b1, b2, out);
}

// round 11
// speedup vs baseline: 2.1721x; 1.0787x over previous
#include <cuda_runtime.h>
#include <cuda_fp16.h>
#include <cstdint>

// ---------------- problem constants ----------------
#define E_   16
#define B_   4096
#define DX_  128
#define DC_  64
#define DIN_ 192
#define DH_  1024
#define DO_  128

#define BM   256            // batch rows per CTA
#define CHN  32             // DH chunk
#define NCH  (DH_/CHN)      // 32 chunks
#define THREADS 256         // 8 warps x 32 rows

// ---------------- smem layout (bytes) ----------------
// fragment-load strides: bytes ≡ 32 or 96 (mod 128) -> conflict-free LDS.64
#define SXC_B 416   // xc row: 192 halves + pad
#define SW1_B 416   // W1 row: 192 halves + pad
#define SW2_B 96    // W2 row: 32 halves + pad

#define OFF_XC 0
#define XC_BYTES (BM*SXC_B)            // 106496
#define OFF_W1 (OFF_XC + XC_BYTES)     // 106496
#define W1_BYTES (CHN*SW1_B)           // 13312 per buf
#define OFF_W2 (OFF_W1 + 2*W1_BYTES)   // 133120
#define W2_BYTES (DO_*SW2_B)           // 12288 per buf
#define OFF_B1 (OFF_W2 + 2*W2_BYTES)   // 157696 (fp32 b1, 1024 floats)
#define OFF_B2 (OFF_B1 + DH_*4)        // 161792 (fp32 b2, 128 floats)
#define SMEM_BYTES (OFF_B2 + DO_*4)    // 162304

// ---------------- prepacked fp16 weights (device globals: allowed) ----------------
__device__ __half g_w1h[(size_t)E_ * DH_ * DIN_];  // 6.3 MB
__device__ __half g_w2h[(size_t)E_ * DO_ * DH_];   // 4.2 MB

// prepack blocks of 16 k-values (weights only)
#define NB1 (E_*DH_*(DIN_/16))     // 196608
#define NB2 (E_*DO_*(DH_/16))      // 131072
#define NBW (NB1+NB2)              // 327680 = 1280*256

// ---------------- helpers ----------------
__device__ __forceinline__ uint32_t s2u(const void* p){
    uint32_t a;
    asm("{ .reg .u64 t; cvta.to.shared.u64 t, %1; cvt.u32.u64 %0, t; }" : "=r"(a) : "l"(p));
    return a;
}
__device__ __forceinline__ uint32_t pkh2(float lo, float hi){
    __half2 h = __floats2half2_rn(lo, hi);       // lo -> lower 16 bits
    return *reinterpret_cast<uint32_t*>(&h);
}
__device__ __forceinline__ void cp16(uint32_t dst, const void* src){
    asm volatile("cp.async.cg.shared.global [%0], [%1], 16;" :: "r"(dst), "l"(src) : "memory");
}
#define CP_COMMIT() asm volatile("cp.async.commit_group;" ::: "memory")
#define CP_WAIT0()  asm volatile("cp.async.wait_group 0;" ::: "memory")
#define CP_WAIT1()  asm volatile("cp.async.wait_group 1;" ::: "memory")

__device__ __forceinline__ void mma_fp16(float c[4],
                                         uint32_t a0, uint32_t a1, uint32_t a2, uint32_t a3,
                                         uint32_t b0, uint32_t b1){
    asm volatile(
        "mma.sync.aligned.m16n8k16.row.col.f32.f16.f16.f32 "
        "{%0,%1,%2,%3}, {%4,%5,%6,%7}, {%8,%9}, {%0,%1,%2,%3};"
        : "+f"(c[0]), "+f"(c[1]), "+f"(c[2]), "+f"(c[3])
        : "r"(a0), "r"(a1), "r"(a2), "r"(a3), "r"(b0), "r"(b1));
}

// pack 16 k-values (4 float4) into the interleaved fp16 block layout:
// halves [k0,k1, k8,k9, k2,k3, k10,k11, k4,k5, k12,k13, k6,k7, k14,k15]
// => thread ct's LDS.64 at byte 8*ct yields (pair 2ct,2ct+1 ; pair 2ct+8,2ct+9)
__device__ __forceinline__ void pack16(const float4 f0, const float4 f1,
                                       const float4 f2, const float4 f3,
                                       uint4& o0, uint4& o1){
    o0.x = pkh2(f0.x, f0.y);   // k0,k1
    o0.y = pkh2(f2.x, f2.y);   // k8,k9
    o0.z = pkh2(f0.z, f0.w);   // k2,k3
    o0.w = pkh2(f2.z, f2.w);   // k10,k11
    o1.x = pkh2(f1.x, f1.y);   // k4,k5
    o1.y = pkh2(f3.x, f3.y);   // k12,k13
    o1.z = pkh2(f1.z, f1.w);   // k6,k7
    o1.w = pkh2(f3.z, f3.w);   // k14,k15
}

// ---------------- prepack (weights only): fp32 -> fp16 interleaved ----------------
__global__ __launch_bounds__(256)
void prepack_kernel(const float* __restrict__ W1, const float* __restrict__ W2)
{
    const int i = blockIdx.x * 256 + threadIdx.x;
    if (i >= NBW) return;

    const float* s;
    __half* dst;
    if (i < NB1) {
        const int p = i % (DIN_/16);
        const int n = (i / (DIN_/16)) % DH_;
        const int e = i / ((DIN_/16) * DH_);
        s   = W1 + ((size_t)e * DH_ + n) * DIN_ + p * 16;
        dst = g_w1h + ((size_t)e * DH_ + n) * DIN_ + p * 16;
    } else {
        const int j = i - NB1;
        const int p = j % (DH_/16);
        const int n = (j / (DH_/16)) % DO_;
        const int e = j / ((DH_/16) * DO_);
        s   = W2 + ((size_t)e * DO_ + n) * DH_ + p * 16;
        dst = g_w2h + ((size_t)e * DO_ + n) * DH_ + p * 16;
    }
    uint4 o0, o1;
    pack16(*(const float4*)(s), *(const float4*)(s + 4),
           *(const float4*)(s + 8), *(const float4*)(s + 12), o0, o1);
    ((uint4*)dst)[0] = o0;
    ((uint4*)dst)[1] = o1;
}

// stage one DH chunk of prepacked W1 + W2 into smem buffer via cp.async
__device__ __forceinline__ void stage_w(uint32_t sb, const __half* __restrict__ w1h,
                                        const __half* __restrict__ w2h, int ch, int buf, int tid)
{
    const __half* src1 = w1h + (size_t)ch * CHN * DIN_;
    const uint32_t d1 = sb + OFF_W1 + buf * W1_BYTES;
    #pragma unroll
    for (int i = 0; i < 3; ++i) {                 // 32 rows x 24 cp16 = 768
        const int idx = tid + i * THREADS;
        const int r = idx / 24, j = idx % 24;
        cp16(d1 + r * SW1_B + j * 16, src1 + (size_t)r * DIN_ + j * 8);
    }
    const __half* src2 = w2h + (size_t)ch * CHN;  // 32-half window per row
    const uint32_t d2 = sb + OFF_W2 + buf * W2_BYTES;
    #pragma unroll
    for (int i = 0; i < 2; ++i) {                 // 128 rows x 4 cp16 = 512
        const int idx = tid + i * THREADS;
        const int r = idx / 4, j = idx % 4;
        cp16(d2 + r * SW2_B + j * 16, src2 + (size_t)r * DH_ + j * 8);
    }
}

// ---------------- main kernel ----------------
__global__ __launch_bounds__(THREADS)
void expert_mlp_fp16b_kernel(const float* __restrict__ x, const float* __restrict__ cond,
                             const float* __restrict__ b1, const float* __restrict__ b2,
                             float* __restrict__ out)
{
    extern __shared__ char smem[];
    float* s_b1 = (float*)(smem + OFF_B1);
    float* s_b2 = (float*)(smem + OFF_B2);
    const uint32_t sb = s2u(smem);

    const int tid  = threadIdx.x;
    const int lane = tid & 31;
    const int wid  = tid >> 5;           // 0..7, 32 rows each
    const int gr   = lane >> 2;
    const int ct   = lane & 3;

    const int e  = blockIdx.x >> 4;      // 16 CTAs per expert
    const int m0 = (blockIdx.x & 15) * BM;

    const float* xp  = x    + (size_t)e * B_ * DX_ + (size_t)m0 * DX_;
    const float* cp_ = cond + (size_t)e * B_ * DC_ + (size_t)m0 * DC_;
    const __half* w1h = g_w1h + (size_t)e * DH_ * DIN_;
    const __half* w2h = g_w2h + (size_t)e * DO_ * DH_;
    float*        op  = out  + (size_t)e * B_ * DO_ + (size_t)m0 * DO_;

    // stage chunk-0 weights (cp.async, overlaps with xc conversion below)
    stage_w(sb, w1h, w2h, 0, 0, tid);
    CP_COMMIT();

    // biases (fp32, natural order): b1 = 1024 floats = 256 threads x float4 (ONE pass)
    {
        const float4 v = *(const float4*)(b1 + (size_t)e * DH_ + tid * 4);
        *(float4*)(s_b1 + tid * 4) = v;
        if (tid < 32) {
            const float4 w = *(const float4*)(b2 + (size_t)e * DO_ + tid * 4);
            *(float4*)(s_b2 + tid * 4) = w;
        }
    }

    // convert xc: fp32 gmem -> fp16 interleaved smem. 256 rows x 12 blocks of 16 k
    #pragma unroll
    for (int i = 0; i < 12; ++i) {
        const int gi = tid + i * THREADS;          // 3072 blocks
        const int r  = gi / 12, p = gi % 12;
        const float* s = (p < 8) ? (xp + (size_t)r * DX_ + p * 16)
                                 : (cp_ + (size_t)r * DC_ + (p - 8) * 16);
        uint4 o0, o1;
        pack16(*(const float4*)(s), *(const float4*)(s + 4),
               *(const float4*)(s + 8), *(const float4*)(s + 12), o0, o1);
        char* d = smem + OFF_XC + r * SXC_B + p * 32;
        *(uint4*)(d)      = o0;
        *(uint4*)(d + 16) = o1;
    }
    CP_WAIT0();
    __syncthreads();

    // y accumulators: warp owns 32 rows x 128 cols -> 2 m-frags x 16 n-tiles x 4 regs
    float yacc[2][16][4];
    #pragma unroll
    for (int m = 0; m < 2; ++m)
        #pragma unroll
        for (int t = 0; t < 16; ++t)
            #pragma unroll
            for (int c = 0; c < 4; ++c) yacc[m][t][c] = 0.0f;

    const int arow = wid * 32 + gr;      // lower A row of m-frag 0 (m-frag 1: +16)
    const char* sxc = smem + OFF_XC;

    for (int ch = 0; ch < NCH; ++ch) {
        const int buf = ch & 1;

        __syncthreads();                 // all warps done reading buf^1 (chunk ch-1)
        if (ch + 1 < NCH) {
            stage_w(sb, w1h, w2h, ch + 1, buf ^ 1, tid);
            CP_COMMIT();
            CP_WAIT1();                  // current buf's group complete
        } else {
            CP_WAIT0();
        }

        const char* w1s = smem + OFF_W1 + buf * W1_BYTES;
        const char* w2s = smem + OFF_W2 + buf * W2_BYTES;

        // ---- MMA1: h[32x32] = xc(warp rows) @ W1chunk^T  (K=192 = 12 k16-steps) ----
        float hacc[2][4][4];
        #pragma unroll
        for (int m = 0; m < 2; ++m)
            #pragma unroll
            for (int t = 0; t < 4; ++t)
                #pragma unroll
                for (int c = 0; c < 4; ++c) hacc[m][t][c] = 0.0f;

        #pragma unroll
        for (int kt = 0; kt < 12; ++kt) {
            const int off = kt * 32 + ct * 8;
            const uint2 u0 = *(const uint2*)(sxc + (arow)      * SXC_B + off);
            const uint2 u1 = *(const uint2*)(sxc + (arow + 8)  * SXC_B + off);
            const uint2 u2 = *(const uint2*)(sxc + (arow + 16) * SXC_B + off);
            const uint2 u3 = *(const uint2*)(sxc + (arow + 24) * SXC_B + off);
            #pragma unroll
            for (int tn = 0; tn < 4; ++tn) {
                const uint2 bw = *(const uint2*)(w1s + (tn * 8 + gr) * SW1_B + off);
                mma_fp16(hacc[0][tn], u0.x, u1.x, u0.y, u1.y, bw.x, bw.y);
                mma_fp16(hacc[1][tn], u2.x, u3.x, u2.y, u3.y, bw.x, bw.y);
            }
        }

        // ---- register epilogue: relu(h + b1) -> fp16 pairs (frag-ready) ----
        uint32_t pk[2][4][2];
        const float* b1s = s_b1 + ch * CHN;
        #pragma unroll
        for (int t = 0; t < 4; ++t) {
            const float2 bb = *(const float2*)(b1s + t * 8 + 2 * ct);
            #pragma unroll
            for (int m = 0; m < 2; ++m) {
                pk[m][t][0] = pkh2(fmaxf(hacc[m][t][0] + bb.x, 0.0f),
                                   fmaxf(hacc[m][t][1] + bb.y, 0.0f));   // row gr
                pk[m][t][1] = pkh2(fmaxf(hacc[m][t][2] + bb.x, 0.0f),
                                   fmaxf(hacc[m][t][3] + bb.y, 0.0f));   // row gr+8
            }
        }

        // ---- MMA2: y[32x128] += h(frags in regs) @ W2chunk^T (K=32 = 2 k16-steps) ----
        #pragma unroll
        for (int ks = 0; ks < 2; ++ks) {
            const int off = ks * 32 + ct * 8;
            #pragma unroll
            for (int tn = 0; tn < 16; ++tn) {
                const uint2 bw = *(const uint2*)(w2s + (tn * 8 + gr) * SW2_B + off);
                mma_fp16(yacc[0][tn], pk[0][2*ks][0], pk[0][2*ks][1],
                         pk[0][2*ks+1][0], pk[0][2*ks+1][1], bw.x, bw.y);
                mma_fp16(yacc[1][tn], pk[1][2*ks][0], pk[1][2*ks][1],
                         pk[1][2*ks+1][0], pk[1][2*ks+1][1], bw.x, bw.y);
            }
        }
    }

    // ---- final epilogue: y + b2 -> gmem ----
    #pragma unroll
    for (int tn = 0; tn < 16; ++tn) {
        const int col = tn * 8 + 2 * ct;
        const float2 bb = *(const float2*)(s_b2 + col);
        #pragma unroll
        for (int m = 0; m < 2; ++m) {
            const int row = arow + m * 16;
            float2 lo, hi;
            lo.x = yacc[m][tn][0] + bb.x;
            lo.y = yacc[m][tn][1] + bb.y;
            hi.x = yacc[m][tn][2] + bb.x;
            hi.y = yacc[m][tn][3] + bb.y;
            *(float2*)(op + (size_t)row * DO_ + col)       = lo;
            *(float2*)(op + (size_t)(row + 8) * DO_ + col) = hi;
        }
    }
}

extern "C" void kernel_launch(void* const* d_in, const int* in_sizes, int n_in,
                              void* d_out, int out_size)
{
    const float* x    = (const float*)d_in[0];
    const float* cond = (const float*)d_in[1];
    const float* W1   = (const float*)d_in[2];
    const float* b1   = (const float*)d_in[3];
    const float* W2   = (const float*)d_in[4];
    const float* b2   = (const float*)d_in[5];
    float* out = (float*)d_out;

    prepack_kernel<<<NBW / 256, 256>>>(W1, W2);

    cudaFuncSetAttribute(expert_mlp_fp16b_kernel,
                         cudaFuncAttributeMaxDynamicSharedMemorySize, SMEM_BYTES);
    const int grid = E_ * (B_ / BM);   // 256 CTAs
    expert_mlp_fp16b_kernel<<<grid, THREADS, SMEM_BYTES>>>(x, cond, b1, b2, out);
}

// round 12
// speedup vs baseline: 2.2525x; 1.0370x over previous
#include <cuda_runtime.h>
#include <cuda_fp16.h>
#include <cstdint>

// ---------------- problem constants ----------------
#define E_   16
#define B_   4096
#define DX_  128
#define DC_  64
#define DIN_ 192
#define DH_  1024
#define DO_  128

#define BM   256            // batch rows per CTA
#define CHN  32             // DH chunk
#define NCH  (DH_/CHN)      // 32 chunks
#define THREADS 256         // 8 warps x 32 rows

// ---------------- smem layout (bytes) ----------------
// xc: 8 row-blocks of 32 rows; per block 12288 B:
//   addr = blk*12288 + kt*1024 + mpair*512 + ((gr^(kt&7))*64) + ct*16 + mhalf*8
// W1 chunk (12288 B): kt*1024 + tnpair*512 + gr*64 + ct*16 + tnhalf*8
// W2 chunk (8192 B):  ks*4096 + tnpair*512 + gr*64 + ct*16 + tnhalf*8
// all fragment loads are LDS.128, 32 lanes hit distinct 16B words within 512B.
#define XC_BLK   12288
#define W1_BYTES 12288
#define W2_BYTES 8192

#define OFF_XC 0
#define XC_BYTES (8*XC_BLK)            // 98304
#define OFF_W1 (OFF_XC + XC_BYTES)     // 98304
#define OFF_W2 (OFF_W1 + 2*W1_BYTES)   // 122880
#define OFF_B1 (OFF_W2 + 2*W2_BYTES)   // 139264 (fp32 b1, 1024 floats)
#define OFF_B2 (OFF_B1 + DH_*4)        // 143360 (fp32 b2, 128 floats)
#define SMEM_BYTES (OFF_B2 + DO_*4)    // 143872

// ---------------- prepacked fp16 weights (device globals: allowed) ----------------
// gmem layout == smem chunk layout (linear cp.async staging)
__device__ __half g_w1h[(size_t)E_ * DH_ * DIN_];  // 6.3 MB, [e][ch][6144 halves]
__device__ __half g_w2h[(size_t)E_ * DO_ * DH_];   // 4.2 MB, [e][ch][4096 halves]

#define NB1 (E_*DH_*(DIN_/16))     // 196608  (one 16-k block each)
#define NB2 (E_*DO_*(DH_/16))      // 131072
#define NBW (NB1+NB2)              // 327680 = 1280*256

// ---------------- helpers ----------------
__device__ __forceinline__ uint32_t s2u(const void* p){
    uint32_t a;
    asm("{ .reg .u64 t; cvta.to.shared.u64 t, %1; cvt.u32.u64 %0, t; }" : "=r"(a) : "l"(p));
    return a;
}
__device__ __forceinline__ uint32_t pkh2(float lo, float hi){
    __half2 h = __floats2half2_rn(lo, hi);       // lo -> lower 16 bits
    return *reinterpret_cast<uint32_t*>(&h);
}
__device__ __forceinline__ void cp16(uint32_t dst, const void* src){
    asm volatile("cp.async.cg.shared.global [%0], [%1], 16;" :: "r"(dst), "l"(src) : "memory");
}
#define CP_COMMIT() asm volatile("cp.async.commit_group;" ::: "memory")
#define CP_WAIT0()  asm volatile("cp.async.wait_group 0;" ::: "memory")
#define CP_WAIT1()  asm volatile("cp.async.wait_group 1;" ::: "memory")

__device__ __forceinline__ void mma_fp16(float c[4],
                                         uint32_t a0, uint32_t a1, uint32_t a2, uint32_t a3,
                                         uint32_t b0, uint32_t b1){
    asm volatile(
        "mma.sync.aligned.m16n8k16.row.col.f32.f16.f16.f32 "
        "{%0,%1,%2,%3}, {%4,%5,%6,%7}, {%8,%9}, {%0,%1,%2,%3};"
        : "+f"(c[0]), "+f"(c[1]), "+f"(c[2]), "+f"(c[3])
        : "r"(a0), "r"(a1), "r"(a2), "r"(a3), "r"(b0), "r"(b1));
}

// frag uint2s for one 16-k block: ct_c = (halves 2c,2c+1 ; halves 2c+8,2c+9)
__device__ __forceinline__ void frag4(const float4 f0, const float4 f1,
                                      const float4 f2, const float4 f3,
                                      uint2& c0, uint2& c1, uint2& c2, uint2& c3){
    c0.x = pkh2(f0.x, f0.y);  c0.y = pkh2(f2.x, f2.y);   // k0,1 | k8,9
    c1.x = pkh2(f0.z, f0.w);  c1.y = pkh2(f2.z, f2.w);   // k2,3 | k10,11
    c2.x = pkh2(f1.x, f1.y);  c2.y = pkh2(f3.x, f3.y);   // k4,5 | k12,13
    c3.x = pkh2(f1.z, f1.w);  c3.y = pkh2(f3.z, f3.w);   // k6,7 | k14,15
}

// ---------------- prepack: fp32 -> fp16, frag-paired chunk layout ----------------
__global__ __launch_bounds__(256)
void prepack_kernel(const float* __restrict__ W1, const float* __restrict__ W2)
{
    const int i = blockIdx.x * 256 + threadIdx.x;
    if (i >= NBW) return;

    if (i < NB1) {
        const int kt = i % 12;
        const int n  = (i / 12) % DH_;
        const int e  = i / (12 * DH_);
        const float* s = W1 + ((size_t)e * DH_ + n) * DIN_ + kt * 16;
        uint2 c0, c1, c2, c3;
        frag4(*(const float4*)(s), *(const float4*)(s + 4),
              *(const float4*)(s + 8), *(const float4*)(s + 12), c0, c1, c2, c3);
        const int ch = n >> 5, nl = n & 31, tn = nl >> 3, g = nl & 7;
        __half* d = g_w1h + (size_t)e * DH_ * DIN_ + ch * 6144
                    + kt * 512 + (tn >> 1) * 256 + g * 32 + (tn & 1) * 4;
        *(uint2*)(d)      = c0;
        *(uint2*)(d + 8)  = c1;
        *(uint2*)(d + 16) = c2;
        *(uint2*)(d + 24) = c3;
    } else {
        const int j = i - NB1;
        const int p = j % 64;              // 16-k block within DH
        const int n = (j / 64) % DO_;
        const int e = j / (64 * DO_);
        const float* s = W2 + ((size_t)e * DO_ + n) * DH_ + p * 16;
        uint2 c0, c1, c2, c3;
        frag4(*(const float4*)(s), *(const float4*)(s + 4),
              *(const float4*)(s + 8), *(const float4*)(s + 12), c0, c1, c2, c3);
        const int ch = p >> 1, ks = p & 1, tn = n >> 3, g = n & 7;
        __half* d = g_w2h + (size_t)e * DO_ * DH_ + ch * 4096
                    + ks * 2048 + (tn >> 1) * 256 + g * 32 + (tn & 1) * 4;
        *(uint2*)(d)      = c0;
        *(uint2*)(d + 8)  = c1;
        *(uint2*)(d + 16) = c2;
        *(uint2*)(d + 24) = c3;
    }
}

// stage one DH chunk of prepacked W1 + W2 (pure linear copy)
__device__ __forceinline__ void stage_w(uint32_t sb, const __half* __restrict__ w1h,
                                        const __half* __restrict__ w2h, int ch, int buf, int tid)
{
    const __half* src1 = w1h + (size_t)ch * 6144;
    const uint32_t d1 = sb + OFF_W1 + buf * W1_BYTES;
    #pragma unroll
    for (int i = 0; i < 3; ++i) {                 // 768 cp16
        const int idx = tid + i * THREADS;
        cp16(d1 + idx * 16, src1 + idx * 8);
    }
    const __half* src2 = w2h + (size_t)ch * 4096;
    const uint32_t d2 = sb + OFF_W2 + buf * W2_BYTES;
    #pragma unroll
    for (int i = 0; i < 2; ++i) {                 // 512 cp16
        const int idx = tid + i * THREADS;
        cp16(d2 + idx * 16, src2 + idx * 8);
    }
}

// ---------------- main kernel ----------------
__global__ __launch_bounds__(THREADS)
void expert_mlp_pk_kernel(const float* __restrict__ x, const float* __restrict__ cond,
                          const float* __restrict__ b1, const float* __restrict__ b2,
                          float* __restrict__ out)
{
    extern __shared__ char smem[];
    float* s_b1 = (float*)(smem + OFF_B1);
    float* s_b2 = (float*)(smem + OFF_B2);
    const uint32_t sb = s2u(smem);

    const int tid  = threadIdx.x;
    const int lane = tid & 31;
    const int wid  = tid >> 5;           // 0..7, 32 rows each
    const int gr   = lane >> 2;
    const int ct   = lane & 3;

    const int e  = blockIdx.x >> 4;      // 16 CTAs per expert
    const int m0 = (blockIdx.x & 15) * BM;

    const float* xp  = x    + (size_t)e * B_ * DX_ + (size_t)m0 * DX_;
    const float* cp_ = cond + (size_t)e * B_ * DC_ + (size_t)m0 * DC_;
    const __half* w1h = g_w1h + (size_t)e * DH_ * DIN_;
    const __half* w2h = g_w2h + (size_t)e * DO_ * DH_;
    float*        op  = out  + (size_t)e * B_ * DO_ + (size_t)m0 * DO_;

    // stage chunk-0 weights (overlaps with xc conversion below)
    stage_w(sb, w1h, w2h, 0, 0, tid);
    CP_COMMIT();

    // biases (fp32, natural order): b1 = 1024 floats = 256 x float4 (one pass)
    {
        const float4 v = *(const float4*)(b1 + (size_t)e * DH_ + tid * 4);
        *(float4*)(s_b1 + tid * 4) = v;
        if (tid < 32) {
            const float4 w = *(const float4*)(b2 + (size_t)e * DO_ + tid * 4);
            *(float4*)(s_b2 + tid * 4) = w;
        }
    }

    // convert xc: fp32 gmem -> fp16 frag-paired smem. 256 rows x 12 blocks of 16 k
    #pragma unroll
    for (int i = 0; i < 12; ++i) {
        const int gi = tid + i * THREADS;          // 3072 blocks
        const int r  = gi / 12, p = gi % 12;
        const float* s = (p < 8) ? (xp + (size_t)r * DX_ + p * 16)
                                 : (cp_ + (size_t)r * DC_ + (p - 8) * 16);
        uint2 c0, c1, c2, c3;
        frag4(*(const float4*)(s), *(const float4*)(s + 4),
              *(const float4*)(s + 8), *(const float4*)(s + 12), c0, c1, c2, c3);
        const int w = r >> 5, r32 = r & 31, m = r32 >> 3, g = r32 & 7;
        char* d = smem + OFF_XC + w * XC_BLK + p * 1024 + (m >> 1) * 512
                  + ((g ^ (p & 7)) * 64) + (m & 1) * 8;
        *(uint2*)(d)      = c0;
        *(uint2*)(d + 16) = c1;
        *(uint2*)(d + 32) = c2;
        *(uint2*)(d + 48) = c3;
    }
    CP_WAIT0();
    __syncthreads();

    // y accumulators: warp owns 32 rows x 128 cols -> 2 m-frags x 16 n-tiles x 4 regs
    float yacc[2][16][4];
    #pragma unroll
    for (int m = 0; m < 2; ++m)
        #pragma unroll
        for (int t = 0; t < 16; ++t)
            #pragma unroll
            for (int c = 0; c < 4; ++c) yacc[m][t][c] = 0.0f;

    const int arow = wid * 32 + gr;      // lower A row of m-frag 0
    const char* xbase = smem + OFF_XC + wid * XC_BLK + ct * 16;
    const int bfo = gr * 64 + ct * 16;   // B-frag lane offset

    for (int ch = 0; ch < NCH; ++ch) {
        const int buf = ch & 1;

        __syncthreads();                 // all warps done reading buf^1 (chunk ch-1)
        if (ch + 1 < NCH) {
            stage_w(sb, w1h, w2h, ch + 1, buf ^ 1, tid);
            CP_COMMIT();
            CP_WAIT1();                  // current buf's group complete
        } else {
            CP_WAIT0();
        }

        const char* w1s = smem + OFF_W1 + buf * W1_BYTES;
        const char* w2s = smem + OFF_W2 + buf * W2_BYTES;

        // ---- MMA1: h[32x32] = xc(warp rows) @ W1chunk^T  (12 k16-steps) ----
        float hacc[2][4][4];
        #pragma unroll
        for (int m = 0; m < 2; ++m)
            #pragma unroll
            for (int t = 0; t < 4; ++t)
                #pragma unroll
                for (int c = 0; c < 4; ++c) hacc[m][t][c] = 0.0f;

        #pragma unroll
        for (int kt = 0; kt < 12; ++kt) {
            const int gx = ((gr ^ (kt & 7)) << 6);
            const uint4 a01 = *(const uint4*)(xbase + kt * 1024 + gx);        // rows gr, gr+8
            const uint4 a23 = *(const uint4*)(xbase + kt * 1024 + 512 + gx);  // rows gr+16, gr+24
            const uint4 b01 = *(const uint4*)(w1s + kt * 1024 + bfo);         // tn0, tn1
            const uint4 b23 = *(const uint4*)(w1s + kt * 1024 + 512 + bfo);   // tn2, tn3
            mma_fp16(hacc[0][0], a01.x, a01.z, a01.y, a01.w, b01.x, b01.y);
            mma_fp16(hacc[0][1], a01.x, a01.z, a01.y, a01.w, b01.z, b01.w);
            mma_fp16(hacc[0][2], a01.x, a01.z, a01.y, a01.w, b23.x, b23.y);
            mma_fp16(hacc[0][3], a01.x, a01.z, a01.y, a01.w, b23.z, b23.w);
            mma_fp16(hacc[1][0], a23.x, a23.z, a23.y, a23.w, b01.x, b01.y);
            mma_fp16(hacc[1][1], a23.x, a23.z, a23.y, a23.w, b01.z, b01.w);
            mma_fp16(hacc[1][2], a23.x, a23.z, a23.y, a23.w, b23.x, b23.y);
            mma_fp16(hacc[1][3], a23.x, a23.z, a23.y, a23.w, b23.z, b23.w);
        }

        // ---- register epilogue: relu(h + b1) -> fp16 pairs (frag-ready) ----
        uint32_t pk[2][4][2];
        const float* b1s = s_b1 + ch * CHN;
        #pragma unroll
        for (int t = 0; t < 4; ++t) {
            const float2 bb = *(const float2*)(b1s + t * 8 + 2 * ct);
            #pragma unroll
            for (int m = 0; m < 2; ++m) {
                pk[m][t][0] = pkh2(fmaxf(hacc[m][t][0] + bb.x, 0.0f),
                                   fmaxf(hacc[m][t][1] + bb.y, 0.0f));   // row gr(+16m)
                pk[m][t][1] = pkh2(fmaxf(hacc[m][t][2] + bb.x, 0.0f),
                                   fmaxf(hacc[m][t][3] + bb.y, 0.0f));   // row gr+8(+16m)
            }
        }

        // ---- MMA2: y[32x128] += h(frags in regs) @ W2chunk^T (2 k16-steps) ----
        #pragma unroll
        for (int ks = 0; ks < 2; ++ks) {
            const char* base = w2s + ks * 4096 + bfo;
            const uint32_t a00 = pk[0][2*ks][0], a01v = pk[0][2*ks][1];
            const uint32_t a02 = pk[0][2*ks+1][0], a03 = pk[0][2*ks+1][1];
            const uint32_t a10 = pk[1][2*ks][0], a11 = pk[1][2*ks][1];
            const uint32_t a12 = pk[1][2*ks+1][0], a13 = pk[1][2*ks+1][1];
            #pragma unroll
            for (int tp = 0; tp < 8; ++tp) {
                const uint4 bw = *(const uint4*)(base + tp * 512);    // tn=2tp, 2tp+1
                mma_fp16(yacc[0][2*tp],   a00, a01v, a02, a03, bw.x, bw.y);
                mma_fp16(yacc[0][2*tp+1], a00, a01v, a02, a03, bw.z, bw.w);
                mma_fp16(yacc[1][2*tp],   a10, a11, a12, a13, bw.x, bw.y);
                mma_fp16(yacc[1][2*tp+1], a10, a11, a12, a13, bw.z, bw.w);
            }
        }
    }

    // ---- final epilogue: y + b2 -> gmem ----
    #pragma unroll
    for (int tn = 0; tn < 16; ++tn) {
        const int col = tn * 8 + 2 * ct;
        const float2 bb = *(const float2*)(s_b2 + col);
        #pragma unroll
        for (int m = 0; m < 2; ++m) {
            const int row = arow + m * 16;
            float2 lo, hi;
            lo.x = yacc[m][tn][0] + bb.x;
            lo.y = yacc[m][tn][1] + bb.y;
            hi.x = yacc[m][tn][2] + bb.x;
            hi.y = yacc[m][tn][3] + bb.y;
            *(float2*)(op + (size_t)row * DO_ + col)       = lo;
            *(float2*)(op + (size_t)(row + 8) * DO_ + col) = hi;
        }
    }
}

extern "C" void kernel_launch(void* const* d_in, const int* in_sizes, int n_in,
                              void* d_out, int out_size)
{
    const float* x    = (const float*)d_in[0];
    const float* cond = (const float*)d_in[1];
    const float* W1   = (const float*)d_in[2];
    const float* b1   = (const float*)d_in[3];
    const float* W2   = (const float*)d_in[4];
    const float* b2   = (const float*)d_in[5];
    float* out = (float*)d_out;

    prepack_kernel<<<NBW / 256, 256>>>(W1, W2);

    cudaFuncSetAttribute(expert_mlp_pk_kernel,
                         cudaFuncAttributeMaxDynamicSharedMemorySize, SMEM_BYTES);
    const int grid = E_ * (B_ / BM);   // 256 CTAs
    expert_mlp_pk_kernel<<<grid, THREADS, SMEM_BYTES>>>(x, cond, b1, b2, out);
}

// round 13
// speedup vs baseline: 2.3114x; 1.0261x over previous
#include <cuda_runtime.h>
#include <cuda_fp16.h>
#include <cstdint>

// ---------------- problem constants ----------------
#define E_   16
#define B_   4096
#define DX_  128
#define DC_  64
#define DIN_ 192
#define DH_  1024
#define DO_  128

#define BM   128            // batch rows per CTA
#define CHN  32             // DH chunk
#define NCH  (DH_/CHN)      // 32 chunks
#define THREADS 128         // 4 warps x 32 rows; 2 CTAs/SM

// ---------------- smem layout (bytes) ----------------
// xc: 4 row-blocks of 32 rows; per block 12288 B:
//   addr = blk*12288 + kt*1024 + mpair*512 + ((gr^(kt&7))*64) + ct*16 + mhalf*8
// W1 chunk (12288 B): kt*1024 + tnpair*512 + gr*64 + ct*16 + tnhalf*8
// W2 chunk (8192 B):  ks*4096 + tnpair*512 + gr*64 + ct*16 + tnhalf*8
#define XC_BLK   12288
#define W1_BYTES 12288
#define W2_BYTES 8192

#define OFF_XC 0
#define XC_BYTES (4*XC_BLK)            // 49152
#define OFF_W1 (OFF_XC + XC_BYTES)     // 49152
#define OFF_W2 (OFF_W1 + 2*W1_BYTES)   // 73728
#define OFF_B1 (OFF_W2 + 2*W2_BYTES)   // 90112 (fp32 b1, 1024 floats)
#define OFF_B2 (OFF_B1 + DH_*4)        // 94208 (fp32 b2, 128 floats)
#define SMEM_BYTES (OFF_B2 + DO_*4)    // 94720  -> 2 CTAs/SM fit

// ---------------- prepacked fp16 weights (device globals: allowed) ----------------
// gmem layout == smem chunk layout (linear cp.async staging)
__device__ __half g_w1h[(size_t)E_ * DH_ * DIN_];  // 6.3 MB, [e][ch][6144 halves]
__device__ __half g_w2h[(size_t)E_ * DO_ * DH_];   // 4.2 MB, [e][ch][4096 halves]

#define NB1 (E_*DH_*(DIN_/16))     // 196608
#define NB2 (E_*DO_*(DH_/16))      // 131072
#define NBW (NB1+NB2)              // 327680 = 1280*256

// ---------------- helpers ----------------
__device__ __forceinline__ uint32_t s2u(const void* p){
    uint32_t a;
    asm("{ .reg .u64 t; cvta.to.shared.u64 t, %1; cvt.u32.u64 %0, t; }" : "=r"(a) : "l"(p));
    return a;
}
__device__ __forceinline__ uint32_t pkh2(float lo, float hi){
    __half2 h = __floats2half2_rn(lo, hi);       // lo -> lower 16 bits
    return *reinterpret_cast<uint32_t*>(&h);
}
__device__ __forceinline__ void cp16(uint32_t dst, const void* src){
    asm volatile("cp.async.cg.shared.global [%0], [%1], 16;" :: "r"(dst), "l"(src) : "memory");
}
#define CP_COMMIT() asm volatile("cp.async.commit_group;" ::: "memory")
#define CP_WAIT0()  asm volatile("cp.async.wait_group 0;" ::: "memory")
#define CP_WAIT1()  asm volatile("cp.async.wait_group 1;" ::: "memory")

__device__ __forceinline__ void mma_fp16(float c[4],
                                         uint32_t a0, uint32_t a1, uint32_t a2, uint32_t a3,
                                         uint32_t b0, uint32_t b1){
    asm volatile(
        "mma.sync.aligned.m16n8k16.row.col.f32.f16.f16.f32 "
        "{%0,%1,%2,%3}, {%4,%5,%6,%7}, {%8,%9}, {%0,%1,%2,%3};"
        : "+f"(c[0]), "+f"(c[1]), "+f"(c[2]), "+f"(c[3])
        : "r"(a0), "r"(a1), "r"(a2), "r"(a3), "r"(b0), "r"(b1));
}

// frag uint2s for one 16-k block: ct_c = (halves 2c,2c+1 ; halves 2c+8,2c+9)
__device__ __forceinline__ void frag4(const float4 f0, const float4 f1,
                                      const float4 f2, const float4 f3,
                                      uint2& c0, uint2& c1, uint2& c2, uint2& c3){
    c0.x = pkh2(f0.x, f0.y);  c0.y = pkh2(f2.x, f2.y);   // k0,1 | k8,9
    c1.x = pkh2(f0.z, f0.w);  c1.y = pkh2(f2.z, f2.w);   // k2,3 | k10,11
    c2.x = pkh2(f1.x, f1.y);  c2.y = pkh2(f3.x, f3.y);   // k4,5 | k12,13
    c3.x = pkh2(f1.z, f1.w);  c3.y = pkh2(f3.z, f3.w);   // k6,7 | k14,15
}

// ---------------- prepack: fp32 -> fp16, frag-paired chunk layout ----------------
__global__ __launch_bounds__(256)
void prepack_kernel(const float* __restrict__ W1, const float* __restrict__ W2)
{
    const int i = blockIdx.x * 256 + threadIdx.x;
    if (i >= NBW) return;

    if (i < NB1) {
        const int kt = i % 12;
        const int n  = (i / 12) % DH_;
        const int e  = i / (12 * DH_);
        const float* s = W1 + ((size_t)e * DH_ + n) * DIN_ + kt * 16;
        uint2 c0, c1, c2, c3;
        frag4(*(const float4*)(s), *(const float4*)(s + 4),
              *(const float4*)(s + 8), *(const float4*)(s + 12), c0, c1, c2, c3);
        const int ch = n >> 5, nl = n & 31, tn = nl >> 3, g = nl & 7;
        __half* d = g_w1h + (size_t)e * DH_ * DIN_ + ch * 6144
                    + kt * 512 + (tn >> 1) * 256 + g * 32 + (tn & 1) * 4;
        *(uint2*)(d)      = c0;
        *(uint2*)(d + 8)  = c1;
        *(uint2*)(d + 16) = c2;
        *(uint2*)(d + 24) = c3;
    } else {
        const int j = i - NB1;
        const int p = j % 64;              // 16-k block within DH
        const int n = (j / 64) % DO_;
        const int e = j / (64 * DO_);
        const float* s = W2 + ((size_t)e * DO_ + n) * DH_ + p * 16;
        uint2 c0, c1, c2, c3;
        frag4(*(const float4*)(s), *(const float4*)(s + 4),
              *(const float4*)(s + 8), *(const float4*)(s + 12), c0, c1, c2, c3);
        const int ch = p >> 1, ks = p & 1, tn = n >> 3, g = n & 7;
        __half* d = g_w2h + (size_t)e * DO_ * DH_ + ch * 4096
                    + ks * 2048 + (tn >> 1) * 256 + g * 32 + (tn & 1) * 4;
        *(uint2*)(d)      = c0;
        *(uint2*)(d + 8)  = c1;
        *(uint2*)(d + 16) = c2;
        *(uint2*)(d + 24) = c3;
    }
}

// stage one DH chunk of prepacked W1 + W2 (pure linear copy)
__device__ __forceinline__ void stage_w(uint32_t sb, const __half* __restrict__ w1h,
                                        const __half* __restrict__ w2h, int ch, int buf, int tid)
{
    const __half* src1 = w1h + (size_t)ch * 6144;
    const uint32_t d1 = sb + OFF_W1 + buf * W1_BYTES;
    #pragma unroll
    for (int i = 0; i < 6; ++i) {                 // 768 cp16
        const int idx = tid + i * THREADS;
        cp16(d1 + idx * 16, src1 + idx * 8);
    }
    const __half* src2 = w2h + (size_t)ch * 4096;
    const uint32_t d2 = sb + OFF_W2 + buf * W2_BYTES;
    #pragma unroll
    for (int i = 0; i < 4; ++i) {                 // 512 cp16
        const int idx = tid + i * THREADS;
        cp16(d2 + idx * 16, src2 + idx * 8);
    }
}

// ---------------- main kernel ----------------
__global__ __launch_bounds__(THREADS)
void expert_mlp_2cta_kernel(const float* __restrict__ x, const float* __restrict__ cond,
                            const float* __restrict__ b1, const float* __restrict__ b2,
                            float* __restrict__ out)
{
    extern __shared__ char smem[];
    float* s_b1 = (float*)(smem + OFF_B1);
    float* s_b2 = (float*)(smem + OFF_B2);
    const uint32_t sb = s2u(smem);

    const int tid  = threadIdx.x;
    const int lane = tid & 31;
    const int wid  = tid >> 5;           // 0..3, 32 rows each
    const int gr   = lane >> 2;
    const int ct   = lane & 3;

    const int e  = blockIdx.x >> 5;      // 32 CTAs per expert
    const int m0 = (blockIdx.x & 31) * BM;

    const float* xp  = x    + (size_t)e * B_ * DX_ + (size_t)m0 * DX_;
    const float* cp_ = cond + (size_t)e * B_ * DC_ + (size_t)m0 * DC_;
    const __half* w1h = g_w1h + (size_t)e * DH_ * DIN_;
    const __half* w2h = g_w2h + (size_t)e * DO_ * DH_;
    float*        op  = out  + (size_t)e * B_ * DO_ + (size_t)m0 * DO_;

    // stage chunk-0 weights (overlaps with xc conversion below)
    stage_w(sb, w1h, w2h, 0, 0, tid);
    CP_COMMIT();

    // biases (fp32): b1 = 1024 floats = 128 threads x float4 x 2 passes
    #pragma unroll
    for (int i = 0; i < 2; ++i) {
        const int t = tid + i * THREADS;
        const float4 v = *(const float4*)(b1 + (size_t)e * DH_ + t * 4);
        *(float4*)(s_b1 + t * 4) = v;
    }
    if (tid < 32) {
        const float4 w = *(const float4*)(b2 + (size_t)e * DO_ + tid * 4);
        *(float4*)(s_b2 + tid * 4) = w;
    }

    // convert xc: fp32 gmem -> fp16 frag-paired smem. 128 rows x 12 blocks of 16 k
    #pragma unroll
    for (int i = 0; i < 12; ++i) {
        const int gi = tid + i * THREADS;          // 1536 blocks
        const int r  = gi / 12, p = gi % 12;
        const float* s = (p < 8) ? (xp + (size_t)r * DX_ + p * 16)
                                 : (cp_ + (size_t)r * DC_ + (p - 8) * 16);
        uint2 c0, c1, c2, c3;
        frag4(*(const float4*)(s), *(const float4*)(s + 4),
              *(const float4*)(s + 8), *(const float4*)(s + 12), c0, c1, c2, c3);
        const int w = r >> 5, r32 = r & 31, m = r32 >> 3, g = r32 & 7;
        char* d = smem + OFF_XC + w * XC_BLK + p * 1024 + (m >> 1) * 512
                  + ((g ^ (p & 7)) * 64) + (m & 1) * 8;
        *(uint2*)(d)      = c0;
        *(uint2*)(d + 16) = c1;
        *(uint2*)(d + 32) = c2;
        *(uint2*)(d + 48) = c3;
    }
    CP_WAIT0();
    __syncthreads();

    // y accumulators: warp owns 32 rows x 128 cols -> 2 m-frags x 16 n-tiles x 4 regs
    float yacc[2][16][4];
    #pragma unroll
    for (int m = 0; m < 2; ++m)
        #pragma unroll
        for (int t = 0; t < 16; ++t)
            #pragma unroll
            for (int c = 0; c < 4; ++c) yacc[m][t][c] = 0.0f;

    const int arow = wid * 32 + gr;      // lower A row of m-frag 0
    const char* xbase = smem + OFF_XC + wid * XC_BLK + ct * 16;
    const int bfo = gr * 64 + ct * 16;   // B-frag lane offset

    for (int ch = 0; ch < NCH; ++ch) {
        const int buf = ch & 1;

        __syncthreads();                 // all warps done reading buf^1 (chunk ch-1)
        if (ch + 1 < NCH) {
            stage_w(sb, w1h, w2h, ch + 1, buf ^ 1, tid);
            CP_COMMIT();
            CP_WAIT1();                  // current buf's group complete
        } else {
            CP_WAIT0();
        }

        const char* w1s = smem + OFF_W1 + buf * W1_BYTES;
        const char* w2s = smem + OFF_W2 + buf * W2_BYTES;

        // ---- MMA1: h[32x32] = xc(warp rows) @ W1chunk^T  (12 k16-steps) ----
        float hacc[2][4][4];
        #pragma unroll
        for (int m = 0; m < 2; ++m)
            #pragma unroll
            for (int t = 0; t < 4; ++t)
                #pragma unroll
                for (int c = 0; c < 4; ++c) hacc[m][t][c] = 0.0f;

        #pragma unroll
        for (int kt = 0; kt < 12; ++kt) {
            const int gx = ((gr ^ (kt & 7)) << 6);
            const uint4 a01 = *(const uint4*)(xbase + kt * 1024 + gx);        // rows gr, gr+8
            const uint4 a23 = *(const uint4*)(xbase + kt * 1024 + 512 + gx);  // rows gr+16, gr+24
            const uint4 b01 = *(const uint4*)(w1s + kt * 1024 + bfo);         // tn0, tn1
            const uint4 b23 = *(const uint4*)(w1s + kt * 1024 + 512 + bfo);   // tn2, tn3
            mma_fp16(hacc[0][0], a01.x, a01.z, a01.y, a01.w, b01.x, b01.y);
            mma_fp16(hacc[0][1], a01.x, a01.z, a01.y, a01.w, b01.z, b01.w);
            mma_fp16(hacc[0][2], a01.x, a01.z, a01.y, a01.w, b23.x, b23.y);
            mma_fp16(hacc[0][3], a01.x, a01.z, a01.y, a01.w, b23.z, b23.w);
            mma_fp16(hacc[1][0], a23.x, a23.z, a23.y, a23.w, b01.x, b01.y);
            mma_fp16(hacc[1][1], a23.x, a23.z, a23.y, a23.w, b01.z, b01.w);
            mma_fp16(hacc[1][2], a23.x, a23.z, a23.y, a23.w, b23.x, b23.y);
            mma_fp16(hacc[1][3], a23.x, a23.z, a23.y, a23.w, b23.z, b23.w);
        }

        // ---- register epilogue: relu(h + b1) -> fp16 pairs (frag-ready) ----
        uint32_t pk[2][4][2];
        const float* b1s = s_b1 + ch * CHN;
        #pragma unroll
        for (int t = 0; t < 4; ++t) {
            const float2 bb = *(const float2*)(b1s + t * 8 + 2 * ct);
            #pragma unroll
            for (int m = 0; m < 2; ++m) {
                pk[m][t][0] = pkh2(fmaxf(hacc[m][t][0] + bb.x, 0.0f),
                                   fmaxf(hacc[m][t][1] + bb.y, 0.0f));   // row gr(+16m)
                pk[m][t][1] = pkh2(fmaxf(hacc[m][t][2] + bb.x, 0.0f),
                                   fmaxf(hacc[m][t][3] + bb.y, 0.0f));   // row gr+8(+16m)
            }
        }

        // ---- MMA2: y[32x128] += h(frags in regs) @ W2chunk^T (2 k16-steps) ----
        #pragma unroll
        for (int ks = 0; ks < 2; ++ks) {
            const char* base = w2s + ks * 4096 + bfo;
            const uint32_t a00 = pk[0][2*ks][0], a01v = pk[0][2*ks][1];
            const uint32_t a02 = pk[0][2*ks+1][0], a03 = pk[0][2*ks+1][1];
            const uint32_t a10 = pk[1][2*ks][0], a11 = pk[1][2*ks][1];
            const uint32_t a12 = pk[1][2*ks+1][0], a13 = pk[1][2*ks+1][1];
            #pragma unroll
            for (int tp = 0; tp < 8; ++tp) {
                const uint4 bw = *(const uint4*)(base + tp * 512);    // tn=2tp, 2tp+1
                mma_fp16(yacc[0][2*tp],   a00, a01v, a02, a03, bw.x, bw.y);
                mma_fp16(yacc[0][2*tp+1], a00, a01v, a02, a03, bw.z, bw.w);
                mma_fp16(yacc[1][2*tp],   a10, a11, a12, a13, bw.x, bw.y);
                mma_fp16(yacc[1][2*tp+1], a10, a11, a12, a13, bw.z, bw.w);
            }
        }
    }

    // ---- final epilogue: y + b2 -> gmem ----
    #pragma unroll
    for (int tn = 0; tn < 16; ++tn) {
        const int col = tn * 8 + 2 * ct;
        const float2 bb = *(const float2*)(s_b2 + col);
        #pragma unroll
        for (int m = 0; m < 2; ++m) {
            const int row = arow + m * 16;
            float2 lo, hi;
            lo.x = yacc[m][tn][0] + bb.x;
            lo.y = yacc[m][tn][1] + bb.y;
            hi.x = yacc[m][tn][2] + bb.x;
            hi.y = yacc[m][tn][3] + bb.y;
            *(float2*)(op + (size_t)row * DO_ + col)       = lo;
            *(float2*)(op + (size_t)(row + 8) * DO_ + col) = hi;
        }
    }
}

extern "C" void kernel_launch(void* const* d_in, const int* in_sizes, int n_in,
                              void* d_out, int out_size)
{
    const float* x    = (const float*)d_in[0];
    const float* cond = (const float*)d_in[1];
    const float* W1   = (const float*)d_in[2];
    const float* b1   = (const float*)d_in[3];
    const float* W2   = (const float*)d_in[4];
    const float* b2   = (const float*)d_in[5];
    float* out = (float*)d_out;

    prepack_kernel<<<NBW / 256, 256>>>(W1, W2);

    cudaFuncSetAttribute(expert_mlp_2cta_kernel,
                         cudaFuncAttributeMaxDynamicSharedMemorySize, SMEM_BYTES);
    const int grid = E_ * (B_ / BM);   // 512 CTAs -> 2 per SM
    expert_mlp_2cta_kernel<<<grid, THREADS, SMEM_BYTES>>>(x, cond, b1, b2, out);
}

// round 15
// speedup vs baseline: 2.5725x; 1.1130x over previous
#include <cuda_runtime.h>
#include <cuda_fp16.h>
#include <cstdint>

// ---------------- problem constants ----------------
#define E_   16
#define B_   4096
#define DX_  128
#define DC_  64
#define DIN_ 192
#define DH_  1024
#define DO_  128

#define BM   64             // batch rows per CTA
#define CHN  32             // DH chunk
#define NCH  (DH_/CHN)      // 32 chunks
#define THREADS 128         // 4 warps x 16 rows; 2 CTAs/SM

// ---------------- smem layout (bytes) ----------------
// xc: 2 row-blocks of 32 rows; per block 12288 B:
//   addr = blk*12288 + kt*1024 + mpair*512 + ((gr^(kt&7))*64) + ct*16 + mhalf*8
// W1 chunk (12288 B): kt*1024 + tnpair*512 + gr*64 + ct*16 + tnhalf*8
// W2 chunk (8192 B):  ks*4096 + tnpair*512 + gr*64 + ct*16 + tnhalf*8
#define XC_BLK   12288
#define W1_BYTES 12288
#define W2_BYTES 8192

#define OFF_XC 0
#define XC_BYTES (2*XC_BLK)            // 24576
#define OFF_W1 (OFF_XC + XC_BYTES)     // 24576
#define OFF_W2 (OFF_W1 + 2*W1_BYTES)   // 49152
#define OFF_B1 (OFF_W2 + 2*W2_BYTES)   // 65536 (fp32 b1, 1024 floats)
#define OFF_B2 (OFF_B1 + DH_*4)        // 69632 (fp32 b2, 128 floats)
#define SMEM_BYTES (OFF_B2 + DO_*4)    // 70144 -> 2 CTAs/SM

// ---------------- prepacked fp16 weights (device globals: allowed) ----------------
__device__ __half g_w1h[(size_t)E_ * DH_ * DIN_];  // 6.3 MB, [e][ch][6144 halves]
__device__ __half g_w2h[(size_t)E_ * DO_ * DH_];   // 4.2 MB, [e][ch][4096 halves]

#define NB1 (E_*DH_*(DIN_/16))     // 196608
#define NB2 (E_*DO_*(DH_/16))      // 131072
#define NBW (NB1+NB2)              // 327680 = 1280*256

// ---------------- helpers ----------------
__device__ __forceinline__ uint32_t s2u(const void* p){
    uint32_t a;
    asm("{ .reg .u64 t; cvta.to.shared.u64 t, %1; cvt.u32.u64 %0, t; }" : "=r"(a) : "l"(p));
    return a;
}
__device__ __forceinline__ uint32_t pkh2(float lo, float hi){
    __half2 h = __floats2half2_rn(lo, hi);       // lo -> lower 16 bits
    return *reinterpret_cast<uint32_t*>(&h);
}
__device__ __forceinline__ void cp16(uint32_t dst, const void* src){
    asm volatile("cp.async.cg.shared.global [%0], [%1], 16;" :: "r"(dst), "l"(src) : "memory");
}
#define CP_COMMIT() asm volatile("cp.async.commit_group;" ::: "memory")
#define CP_WAIT0()  asm volatile("cp.async.wait_group 0;" ::: "memory")

__device__ __forceinline__ void mma_fp16(float c[4],
                                         uint32_t a0, uint32_t a1, uint32_t a2, uint32_t a3,
                                         uint32_t b0, uint32_t b1){
    asm volatile(
        "mma.sync.aligned.m16n8k16.row.col.f32.f16.f16.f32 "
        "{%0,%1,%2,%3}, {%4,%5,%6,%7}, {%8,%9}, {%0,%1,%2,%3};"
        : "+f"(c[0]), "+f"(c[1]), "+f"(c[2]), "+f"(c[3])
        : "r"(a0), "r"(a1), "r"(a2), "r"(a3), "r"(b0), "r"(b1));
}

// frag uint2s for one 16-k block: ct_c = (halves 2c,2c+1 ; halves 2c+8,2c+9)
__device__ __forceinline__ void frag4(const float4 f0, const float4 f1,
                                      const float4 f2, const float4 f3,
                                      uint2& c0, uint2& c1, uint2& c2, uint2& c3){
    c0.x = pkh2(f0.x, f0.y);  c0.y = pkh2(f2.x, f2.y);   // k0,1 | k8,9
    c1.x = pkh2(f0.z, f0.w);  c1.y = pkh2(f2.z, f2.w);   // k2,3 | k10,11
    c2.x = pkh2(f1.x, f1.y);  c2.y = pkh2(f3.x, f3.y);   // k4,5 | k12,13
    c3.x = pkh2(f1.z, f1.w);  c3.y = pkh2(f3.z, f3.w);   // k6,7 | k14,15
}

// ---------------- prepack: fp32 -> fp16, frag-paired chunk layout ----------------
__global__ __launch_bounds__(256)
void prepack_kernel(const float* __restrict__ W1, const float* __restrict__ W2)
{
    const int i = blockIdx.x * 256 + threadIdx.x;
    if (i >= NBW) return;

    if (i < NB1) {
        const int kt = i % 12;
        const int n  = (i / 12) % DH_;
        const int e  = i / (12 * DH_);
        const float* s = W1 + ((size_t)e * DH_ + n) * DIN_ + kt * 16;
        uint2 c0, c1, c2, c3;
        frag4(*(const float4*)(s), *(const float4*)(s + 4),
              *(const float4*)(s + 8), *(const float4*)(s + 12), c0, c1, c2, c3);
        const int ch = n >> 5, nl = n & 31, tn = nl >> 3, g = nl & 7;
        __half* d = g_w1h + (size_t)e * DH_ * DIN_ + ch * 6144
                    + kt * 512 + (tn >> 1) * 256 + g * 32 + (tn & 1) * 4;
        *(uint2*)(d)      = c0;
        *(uint2*)(d + 8)  = c1;
        *(uint2*)(d + 16) = c2;
        *(uint2*)(d + 24) = c3;
    } else {
        const int j = i - NB1;
        const int p = j % 64;              // 16-k block within DH
        const int n = (j / 64) % DO_;
        const int e = j / (64 * DO_);
        const float* s = W2 + ((size_t)e * DO_ + n) * DH_ + p * 16;
        uint2 c0, c1, c2, c3;
        frag4(*(const float4*)(s), *(const float4*)(s + 4),
              *(const float4*)(s + 8), *(const float4*)(s + 12), c0, c1, c2, c3);
        const int ch = p >> 1, ks = p & 1, tn = n >> 3, g = n & 7;
        __half* d = g_w2h + (size_t)e * DO_ * DH_ + ch * 4096
                    + ks * 2048 + (tn >> 1) * 256 + g * 32 + (tn & 1) * 4;
        *(uint2*)(d)      = c0;
        *(uint2*)(d + 8)  = c1;
        *(uint2*)(d + 16) = c2;
        *(uint2*)(d + 24) = c3;
    }
}

// stage one DH chunk of prepacked W1 + W2 (pure linear copy)
__device__ __forceinline__ void stage_w(uint32_t sb, const __half* __restrict__ w1h,
                                        const __half* __restrict__ w2h, int ch, int buf, int tid)
{
    const __half* src1 = w1h + (size_t)ch * 6144;
    const uint32_t d1 = sb + OFF_W1 + buf * W1_BYTES;
    #pragma unroll
    for (int i = 0; i < 6; ++i) {                 // 768 cp16
        const int idx = tid + i * THREADS;
        cp16(d1 + idx * 16, src1 + idx * 8);
    }
    const __half* src2 = w2h + (size_t)ch * 4096;
    const uint32_t d2 = sb + OFF_W2 + buf * W2_BYTES;
    #pragma unroll
    for (int i = 0; i < 4; ++i) {                 // 512 cp16
        const int idx = tid + i * THREADS;
        cp16(d2 + idx * 16, src2 + idx * 8);
    }
}

// ---------------- main kernel ----------------
__global__ __launch_bounds__(THREADS)
void expert_mlp_areg2_kernel(const float* __restrict__ x, const float* __restrict__ cond,
                             const float* __restrict__ b1, const float* __restrict__ b2,
                             float* __restrict__ out)
{
    extern __shared__ char smem[];
    float* s_b1 = (float*)(smem + OFF_B1);
    float* s_b2 = (float*)(smem + OFF_B2);
    const uint32_t sb = s2u(smem);

    const int tid  = threadIdx.x;
    const int lane = tid & 31;
    const int wid  = tid >> 5;           // 0..3, 16 rows each
    const int gr   = lane >> 2;
    const int ct   = lane & 3;

    const int e  = blockIdx.x >> 6;      // 64 CTAs per expert
    const int m0 = (blockIdx.x & 63) * BM;

    const float* xp  = x    + (size_t)e * B_ * DX_ + (size_t)m0 * DX_;
    const float* cp_ = cond + (size_t)e * B_ * DC_ + (size_t)m0 * DC_;
    const __half* w1h = g_w1h + (size_t)e * DH_ * DIN_;
    const __half* w2h = g_w2h + (size_t)e * DO_ * DH_;
    float*        op  = out  + (size_t)e * B_ * DO_ + (size_t)m0 * DO_;

    // stage chunk-0 weights (overlaps with xc conversion below)
    stage_w(sb, w1h, w2h, 0, 0, tid);
    CP_COMMIT();

    // biases (fp32): b1 = 1024 floats = 128 threads x float4 x 2 passes
    #pragma unroll
    for (int i = 0; i < 2; ++i) {
        const int t = tid + i * THREADS;
        const float4 v = *(const float4*)(b1 + (size_t)e * DH_ + t * 4);
        *(float4*)(s_b1 + t * 4) = v;
    }
    if (tid < 32) {
        const float4 w = *(const float4*)(b2 + (size_t)e * DO_ + tid * 4);
        *(float4*)(s_b2 + tid * 4) = w;
    }

    // convert xc: fp32 gmem -> fp16 frag-paired smem. 64 rows x 12 blocks of 16 k
    #pragma unroll
    for (int i = 0; i < 6; ++i) {
        const int gi = tid + i * THREADS;          // 768 blocks
        const int r  = gi / 12, p = gi % 12;
        const float* s = (p < 8) ? (xp + (size_t)r * DX_ + p * 16)
                                 : (cp_ + (size_t)r * DC_ + (p - 8) * 16);
        uint2 c0, c1, c2, c3;
        frag4(*(const float4*)(s), *(const float4*)(s + 4),
              *(const float4*)(s + 8), *(const float4*)(s + 12), c0, c1, c2, c3);
        const int w = r >> 5, r32 = r & 31, m = r32 >> 3, g = r32 & 7;
        char* d = smem + OFF_XC + w * XC_BLK + p * 1024 + (m >> 1) * 512
                  + ((g ^ (p & 7)) * 64) + (m & 1) * 8;
        *(uint2*)(d)      = c0;
        *(uint2*)(d + 16) = c1;
        *(uint2*)(d + 32) = c2;
        *(uint2*)(d + 48) = c3;
    }
    // correct cp.async handshake: every thread drains ALL its copies, THEN barrier
    CP_WAIT0();
    __syncthreads();

    // ---- load this warp's A fragments ONCE into registers (48 regs) ----
    // warp w owns rows 16w..16w+15: block w>>1, m-pair w&1
    uint4 xa[12];
    {
        const char* xb = smem + OFF_XC + (wid >> 1) * XC_BLK + (wid & 1) * 512 + ct * 16;
        #pragma unroll
        for (int kt = 0; kt < 12; ++kt)
            xa[kt] = *(const uint4*)(xb + kt * 1024 + ((gr ^ (kt & 7)) << 6));
    }

    // y accumulators: warp owns 16 rows x 128 cols -> 16 n-tiles x 4 regs
    float yacc[16][4];
    #pragma unroll
    for (int t = 0; t < 16; ++t)
        #pragma unroll
        for (int c = 0; c < 4; ++c) yacc[t][c] = 0.0f;

    const int arow = wid * 16 + gr;      // this thread's lower A row
    const int bfo = gr * 64 + ct * 16;   // B-frag lane offset

    // loop invariant at entry: chunk ch's weights are COMPLETE (all threads) and
    // published by the trailing CP_WAIT0 + __syncthreads of the previous iteration
    // (or the prologue for ch=0).
    for (int ch = 0; ch < NCH; ++ch) {
        const int buf = ch & 1;

        // stage next chunk into buf^1 (whose readers finished last iteration)
        if (ch + 1 < NCH) {
            stage_w(sb, w1h, w2h, ch + 1, buf ^ 1, tid);
            CP_COMMIT();
        }

        const char* w1s = smem + OFF_W1 + buf * W1_BYTES;
        const char* w2s = smem + OFF_W2 + buf * W2_BYTES;

        // ---- MMA1: h[16x32] = xc(regs) @ W1chunk^T  (12 k16-steps) ----
        float hacc[4][4];
        #pragma unroll
        for (int t = 0; t < 4; ++t)
            #pragma unroll
            for (int c = 0; c < 4; ++c) hacc[t][c] = 0.0f;

        #pragma unroll
        for (int kt = 0; kt < 12; ++kt) {
            const uint4 b01 = *(const uint4*)(w1s + kt * 1024 + bfo);        // tn0, tn1
            const uint4 b23 = *(const uint4*)(w1s + kt * 1024 + 512 + bfo);  // tn2, tn3
            const uint4 a = xa[kt];
            mma_fp16(hacc[0], a.x, a.z, a.y, a.w, b01.x, b01.y);
            mma_fp16(hacc[1], a.x, a.z, a.y, a.w, b01.z, b01.w);
            mma_fp16(hacc[2], a.x, a.z, a.y, a.w, b23.x, b23.y);
            mma_fp16(hacc[3], a.x, a.z, a.y, a.w, b23.z, b23.w);
        }

        // ---- register epilogue: relu(h + b1) -> fp16 pairs (frag-ready) ----
        uint32_t pk[4][2];
        const float* b1s = s_b1 + ch * CHN;
        #pragma unroll
        for (int t = 0; t < 4; ++t) {
            const float2 bb = *(const float2*)(b1s + t * 8 + 2 * ct);
            pk[t][0] = pkh2(fmaxf(hacc[t][0] + bb.x, 0.0f),
                            fmaxf(hacc[t][1] + bb.y, 0.0f));   // row gr
            pk[t][1] = pkh2(fmaxf(hacc[t][2] + bb.x, 0.0f),
                            fmaxf(hacc[t][3] + bb.y, 0.0f));   // row gr+8
        }

        // ---- MMA2: y[16x128] += h(frags in regs) @ W2chunk^T (2 k16-steps) ----
        #pragma unroll
        for (int ks = 0; ks < 2; ++ks) {
            const char* base = w2s + ks * 4096 + bfo;
            const uint32_t a0 = pk[2*ks][0],   a1 = pk[2*ks][1];
            const uint32_t a2 = pk[2*ks+1][0], a3 = pk[2*ks+1][1];
            #pragma unroll
            for (int tp = 0; tp < 8; ++tp) {
                const uint4 bw = *(const uint4*)(base + tp * 512);    // tn=2tp, 2tp+1
                mma_fp16(yacc[2*tp],   a0, a1, a2, a3, bw.x, bw.y);
                mma_fp16(yacc[2*tp+1], a0, a1, a2, a3, bw.z, bw.w);
            }
        }

        // drain my copies of chunk ch+1, then publish to all threads.
        // (wait is ~free: copies were issued a full chunk-compute ago)
        CP_WAIT0();
        __syncthreads();
    }

    // ---- final epilogue: y + b2 -> gmem ----
    #pragma unroll
    for (int tn = 0; tn < 16; ++tn) {
        const int col = tn * 8 + 2 * ct;
        const float2 bb = *(const float2*)(s_b2 + col);
        float2 lo, hi;
        lo.x = yacc[tn][0] + bb.x;
        lo.y = yacc[tn][1] + bb.y;
        hi.x = yacc[tn][2] + bb.x;
        hi.y = yacc[tn][3] + bb.y;
        *(float2*)(op + (size_t)arow * DO_ + col)       = lo;
        *(float2*)(op + (size_t)(arow + 8) * DO_ + col) = hi;
    }
}

extern "C" void kernel_launch(void* const* d_in, const int* in_sizes, int n_in,
                              void* d_out, int out_size)
{
    const float* x    = (const float*)d_in[0];
    const float* cond = (const float*)d_in[1];
    const float* W1   = (const float*)d_in[2];
    const float* b1   = (const float*)d_in[3];
    const float* W2   = (const float*)d_in[4];
    const float* b2   = (const float*)d_in[5];
    float* out = (float*)d_out;

    prepack_kernel<<<NBW / 256, 256>>>(W1, W2);

    cudaFuncSetAttribute(expert_mlp_areg2_kernel,
                         cudaFuncAttributeMaxDynamicSharedMemorySize, SMEM_BYTES);
    const int grid = E_ * (B_ / BM);   // 1024 CTAs -> 2 per SM
    expert_mlp_areg2_kernel<<<grid, THREADS, SMEM_BYTES>>>(x, cond, b1, b2, out);
}